// round 8
// baseline (speedup 1.0000x reference)
#include <cuda_runtime.h>
#include <math.h>

#define NN 51200      // nodes
#define EE 409600     // edges (without self loops)
#define BB 256        // batch
#define NHOST 13
#define NR  (BB * NHOST)   // 3328 gathered host rows
#define IN_F 64
#define H1 256
#define H2 64
#define ZN 65536      // max(NN, BB*H1) — elements to zero

typedef unsigned long long u64;

// ---------------- scratch (static device globals; no runtime alloc) -------
__device__ int   d_cnt[NN];
__device__ int   d_off[NN + 1];
__device__ int   d_cur[NN];
__device__ int   d_csr[EE];
__device__ int   d_flag[NN];
__device__ int   d_ishost[NN];
__device__ int   d_list[NN];
__device__ int   d_nf;
__device__ float d_dinv[NN];
__device__ float d_xw[(size_t)NN * H1];    // dinv * (x @ W1)
__device__ float d_x1[(size_t)NN * H1];    // relu(agg1 + b1) on frontier rows
__device__ float d_xw2[(size_t)NN * H2];   // dinv * (x1 @ W2), frontier rows only
__device__ float d_x2h[(size_t)NR * H2];   // layer-2 output, host rows (packed)
__device__ float d_g[(size_t)BB * H1];     // global state
__device__ float d_al[(size_t)NR * H1];    // attention logits (packed host rows)
__device__ float d_fl[(size_t)NR * H1];    // attention feats
__device__ float d_cat[(size_t)BB * 512];  // [out(H) | g(256)] per batch, stride 512

// ---------------- zero ------------------------------------------------------
__global__ void k_zero() {
    int i = blockIdx.x * blockDim.x + threadIdx.x;
    if (i < NN) { d_cnt[i] = 0; d_flag[i] = 0; d_ishost[i] = 0; }
    if (i < BB * H1) d_g[i] = 0.f;
    if (i == 0) d_nf = 0;
}

__global__ void k_count_mh(const int* __restrict__ dst, const int* __restrict__ hidx) {
    int e = blockIdx.x * blockDim.x + threadIdx.x;
    if (e < EE) atomicAdd(&d_cnt[dst[e]], 1);
    if (e < NR) {
        int n = hidx[e];
        d_ishost[n] = 1;
        d_flag[n] = 1;
    }
}

// 1 block, 1024 threads, 50 items each
__global__ void k_scan() {
    __shared__ int part[1024];
    int t = threadIdx.x;
    int base = t * 50;
    int s = 0;
    for (int i = 0; i < 50; i++) s += d_cnt[base + i];
    part[t] = s;
    __syncthreads();
    for (int d = 1; d < 1024; d <<= 1) {
        int v = part[t];
        int add = (t >= d) ? part[t - d] : 0;
        __syncthreads();
        part[t] = v + add;
        __syncthreads();
    }
    int run = part[t] - s;
    for (int i = 0; i < 50; i++) {
        int c = d_cnt[base + i];
        d_off[base + i] = run;
        d_cur[base + i] = run;
        d_dinv[base + i] = rsqrtf((float)(c + 1));
        run += c;
    }
    if (t == 1023) d_off[NN] = run;
}

__global__ void k_fill_me(const int* __restrict__ src, const int* __restrict__ dst) {
    int e = blockIdx.x * blockDim.x + threadIdx.x;
    if (e < EE) {
        int d = dst[e];
        int s = src[e];
        int p = atomicAdd(&d_cur[d], 1);
        d_csr[p] = s;
        if (d_ishost[d]) d_flag[s] = 1;
    }
}

__global__ void k_mklist() {
    int i = blockIdx.x * blockDim.x + threadIdx.x;
    if (i < NN && d_flag[i]) {
        int p = atomicAdd(&d_nf, 1);
        d_list[p] = i;
    }
}

// ---------------- GEMM1: xw = dinv * (x @ W1)  [51200,64]x[64,256] ---------
#define G1R 32
__global__ void k_gemm1(const float* __restrict__ x, const float* __restrict__ W1) {
    __shared__ float xs[IN_F][G1R + 2];
    int r0 = blockIdx.x * G1R;
    int t = threadIdx.x; // 256
    int rg = t >> 6;
    int cg = t & 63;
    for (int i = t; i < G1R * IN_F; i += 256) {
        int r = i >> 6, k = i & 63;
        xs[k][r] = x[(size_t)(r0 + r) * IN_F + k];
    }
    __syncthreads();
    u64 acc[4][4];
#pragma unroll
    for (int p = 0; p < 4; p++)
#pragma unroll
        for (int c = 0; c < 4; c++) acc[p][c] = 0ull;
    for (int k = 0; k < IN_F; k++) {
        float4 w4 = *reinterpret_cast<const float4*>(&W1[k * H1 + cg * 4]);
        u64 wd[4];
        asm("mov.b64 %0, {%1, %1};" : "=l"(wd[0]) : "f"(w4.x));
        asm("mov.b64 %0, {%1, %1};" : "=l"(wd[1]) : "f"(w4.y));
        asm("mov.b64 %0, {%1, %1};" : "=l"(wd[2]) : "f"(w4.z));
        asm("mov.b64 %0, {%1, %1};" : "=l"(wd[3]) : "f"(w4.w));
        u64 xp[4];
#pragma unroll
        for (int p = 0; p < 4; p++)
            xp[p] = *reinterpret_cast<const u64*>(&xs[k][rg * 8 + 2 * p]);
#pragma unroll
        for (int p = 0; p < 4; p++)
#pragma unroll
            for (int c = 0; c < 4; c++)
                asm("fma.rn.f32x2 %0, %1, %2, %0;" : "+l"(acc[p][c]) : "l"(xp[p]), "l"(wd[c]));
    }
#pragma unroll
    for (int p = 0; p < 4; p++) {
        float lo[4], hi[4];
#pragma unroll
        for (int c = 0; c < 4; c++)
            asm("mov.b64 {%0, %1}, %2;" : "=f"(lo[c]), "=f"(hi[c]) : "l"(acc[p][c]));
        int ra = r0 + rg * 8 + 2 * p;
        float da = d_dinv[ra], db = d_dinv[ra + 1];
        float4 oa = make_float4(da * lo[0], da * lo[1], da * lo[2], da * lo[3]);
        float4 ob = make_float4(db * hi[0], db * hi[1], db * hi[2], db * hi[3]);
        *reinterpret_cast<float4*>(&d_xw[(size_t)ra * H1 + cg * 4])       = oa;
        *reinterpret_cast<float4*>(&d_xw[(size_t)(ra + 1) * H1 + cg * 4]) = ob;
    }
}

// ---------------- layer-1 max aggregation (frontier list) ------------------
__global__ void k_agg1(const float* __restrict__ b1) {
    int bi = blockIdx.x;
    if (bi >= d_nf) return;
    int i = d_list[bi];
    int t = threadIdx.x; // 256
    __shared__ int nbr[256];
    float m = d_xw[(size_t)i * H1 + t];
    int e0 = d_off[i], e1 = d_off[i + 1];
    for (int base = e0; base < e1; base += 256) {
        int n = min(256, e1 - base);
        __syncthreads();
        if (t < n) nbr[t] = d_csr[base + t];
        __syncthreads();
        int e = 0;
        for (; e + 4 <= n; e += 4) {
            int s0 = nbr[e], s1 = nbr[e + 1], s2 = nbr[e + 2], s3 = nbr[e + 3];
            float v0 = __ldg(&d_xw[(size_t)s0 * H1 + t]);
            float v1 = __ldg(&d_xw[(size_t)s1 * H1 + t]);
            float v2 = __ldg(&d_xw[(size_t)s2 * H1 + t]);
            float v3 = __ldg(&d_xw[(size_t)s3 * H1 + t]);
            m = fmaxf(m, fmaxf(fmaxf(v0, v1), fmaxf(v2, v3)));
        }
        for (; e < n; e++)
            m = fmaxf(m, __ldg(&d_xw[(size_t)nbr[e] * H1 + t]));
    }
    d_x1[(size_t)i * H1 + t] = fmaxf(d_dinv[i] * m + b1[t], 0.f);
}

// ---------------- GEMM2 on frontier rows: xw2 = dinv * (x1 @ W2) -----------
#define G2R 128
__global__ void k_gemm2(const float* __restrict__ W2) {
    int r0 = blockIdx.x * G2R;
    int nf = d_nf;
    if (r0 >= nf) return;
    __shared__ float xs[64][G2R + 2];
    __shared__ int rows[G2R];
    int t = threadIdx.x;      // 256
    int rg = t >> 4;
    int cg = t & 15;
    if (t < G2R) rows[t] = d_list[min(r0 + t, nf - 1)];
    __syncthreads();
    u64 acc[4][4];
#pragma unroll
    for (int p = 0; p < 4; p++)
#pragma unroll
        for (int c = 0; c < 4; c++) acc[p][c] = 0ull;
    for (int kc = 0; kc < H1; kc += 64) {
        __syncthreads();
        for (int i = t; i < G2R * 64; i += 256) {
            int r = i >> 6, k = i & 63;
            xs[k][r] = d_x1[(size_t)rows[r] * H1 + kc + k];
        }
        __syncthreads();
        for (int k = 0; k < 64; k++) {
            float4 w4 = *reinterpret_cast<const float4*>(&W2[(kc + k) * H2 + cg * 4]);
            u64 wd[4];
            asm("mov.b64 %0, {%1, %1};" : "=l"(wd[0]) : "f"(w4.x));
            asm("mov.b64 %0, {%1, %1};" : "=l"(wd[1]) : "f"(w4.y));
            asm("mov.b64 %0, {%1, %1};" : "=l"(wd[2]) : "f"(w4.z));
            asm("mov.b64 %0, {%1, %1};" : "=l"(wd[3]) : "f"(w4.w));
            u64 xp[4];
#pragma unroll
            for (int p = 0; p < 4; p++)
                xp[p] = *reinterpret_cast<const u64*>(&xs[k][rg * 8 + 2 * p]);
#pragma unroll
            for (int p = 0; p < 4; p++)
#pragma unroll
                for (int c = 0; c < 4; c++)
                    asm("fma.rn.f32x2 %0, %1, %2, %0;" : "+l"(acc[p][c]) : "l"(xp[p]), "l"(wd[c]));
        }
    }
#pragma unroll
    for (int p = 0; p < 4; p++) {
        float lo[4], hi[4];
#pragma unroll
        for (int c = 0; c < 4; c++)
            asm("mov.b64 {%0, %1}, %2;" : "=f"(lo[c]), "=f"(hi[c]) : "l"(acc[p][c]));
        int rla = rg * 8 + 2 * p;
        int ga = rows[rla], gb2 = rows[rla + 1];
        float da = d_dinv[ga], db = d_dinv[gb2];
        float4 oa = make_float4(da * lo[0], da * lo[1], da * lo[2], da * lo[3]);
        float4 ob = make_float4(db * hi[0], db * hi[1], db * hi[2], db * hi[3]);
        *reinterpret_cast<float4*>(&d_xw2[(size_t)ga * H2 + cg * 4])  = oa;
        *reinterpret_cast<float4*>(&d_xw2[(size_t)gb2 * H2 + cg * 4]) = ob;
    }
}

// ---------------- layer-2 max aggregation (HOST rows, packed out) ----------
__global__ void k_agg2(const int* __restrict__ hidx, const float* __restrict__ b2) {
    int hi = blockIdx.x;       // 0..NR-1
    int t = threadIdx.x;       // 64
    __shared__ int nbr[64];
    int node = hidx[hi];
    float m = d_xw2[(size_t)node * H2 + t];
    int e0 = d_off[node], e1 = d_off[node + 1];
    for (int base = e0; base < e1; base += 64) {
        int n = min(64, e1 - base);
        __syncthreads();
        if (t < n) nbr[t] = d_csr[base + t];
        __syncthreads();
        int e = 0;
        for (; e + 4 <= n; e += 4) {
            int s0 = nbr[e], s1 = nbr[e + 1], s2 = nbr[e + 2], s3 = nbr[e + 3];
            float v0 = __ldg(&d_xw2[(size_t)s0 * H2 + t]);
            float v1 = __ldg(&d_xw2[(size_t)s1 * H2 + t]);
            float v2 = __ldg(&d_xw2[(size_t)s2 * H2 + t]);
            float v3 = __ldg(&d_xw2[(size_t)s3 * H2 + t]);
            m = fmaxf(m, fmaxf(fmaxf(v0, v1), fmaxf(v2, v3)));
        }
        for (; e < n; e++)
            m = fmaxf(m, __ldg(&d_xw2[(size_t)nbr[e] * H2 + t]));
    }
    d_x2h[(size_t)hi * H2 + t] = fmaxf(d_dinv[node] * m + b2[t], 0.f);
}

// ---------------- k_lin: out[NR,H] = gather(v)[NR,KD] @ W[KD,H] + bias -----
// 256 threads; col groups H/4; row groups 1024/H; 8 rows/thread (4 u64 pairs).
template <int KD, int H, int RB>
__global__ void k_lin(const float* __restrict__ v, const int* __restrict__ hidx,
                      const float* __restrict__ W, const float* __restrict__ bias,
                      float* __restrict__ out) {
    __shared__ float xs[64][RB + 2];
    __shared__ int rows[RB];
    constexpr int CGN = H / 4;           // col groups
    int r0 = blockIdx.x * RB;
    int t = threadIdx.x;                 // 256
    int cg = t % CGN;
    int rg = t / CGN;                    // 1024/H row groups
    if (t < RB) rows[t] = hidx ? hidx[r0 + t] : (r0 + t);
    __syncthreads();
    u64 acc[4][4];
#pragma unroll
    for (int p = 0; p < 4; p++)
#pragma unroll
        for (int c = 0; c < 4; c++) acc[p][c] = 0ull;
    for (int kc = 0; kc < KD; kc += 64) {
        __syncthreads();
        for (int i = t; i < RB * 64; i += 256) {
            int r = i >> 6, k = i & 63;
            xs[k][r] = v[(size_t)rows[r] * KD + kc + k];
        }
        __syncthreads();
        for (int k = 0; k < 64; k++) {
            float4 w4 = *reinterpret_cast<const float4*>(&W[(size_t)(kc + k) * H + cg * 4]);
            u64 wd[4];
            asm("mov.b64 %0, {%1, %1};" : "=l"(wd[0]) : "f"(w4.x));
            asm("mov.b64 %0, {%1, %1};" : "=l"(wd[1]) : "f"(w4.y));
            asm("mov.b64 %0, {%1, %1};" : "=l"(wd[2]) : "f"(w4.z));
            asm("mov.b64 %0, {%1, %1};" : "=l"(wd[3]) : "f"(w4.w));
            u64 xp[4];
#pragma unroll
            for (int p = 0; p < 4; p++)
                xp[p] = *reinterpret_cast<const u64*>(&xs[k][rg * 8 + 2 * p]);
#pragma unroll
            for (int p = 0; p < 4; p++)
#pragma unroll
                for (int c = 0; c < 4; c++)
                    asm("fma.rn.f32x2 %0, %1, %2, %0;" : "+l"(acc[p][c]) : "l"(xp[p]), "l"(wd[c]));
        }
    }
    float4 b4 = *reinterpret_cast<const float4*>(&bias[cg * 4]);
#pragma unroll
    for (int p = 0; p < 4; p++) {
        float lo[4], hi[4];
#pragma unroll
        for (int c = 0; c < 4; c++)
            asm("mov.b64 {%0, %1}, %2;" : "=f"(lo[c]), "=f"(hi[c]) : "l"(acc[p][c]));
        int ra = r0 + rg * 8 + 2 * p;
        float4 oa = make_float4(lo[0] + b4.x, lo[1] + b4.y, lo[2] + b4.z, lo[3] + b4.w);
        float4 ob = make_float4(hi[0] + b4.x, hi[1] + b4.y, hi[2] + b4.z, hi[3] + b4.w);
        *reinterpret_cast<float4*>(&out[(size_t)ra * H + cg * 4])       = oa;
        *reinterpret_cast<float4*>(&out[(size_t)(ra + 1) * H + cg * 4]) = ob;
    }
}

// ---------------- k_soft: softmax over H + weighted host sum → cat ---------
// grid BB, 256 threads. cat[b] = [ out(H) | g(H1) ], stride 512.
template <int H>
__global__ void k_soft(const float* __restrict__ albuf, const float* __restrict__ flbuf) {
    int b = blockIdx.x;
    int t = threadIdx.x;       // 256
    int lane = t & 31, w = t >> 5;  // 8 warps
    __shared__ float al_s[NHOST * H];
    __shared__ float mx[NHOST], rinv[NHOST];
    for (int i = t; i < NHOST * H; i += 256)
        al_s[i] = albuf[(size_t)(b * NHOST) * H + i];
    __syncthreads();
    for (int h = w; h < NHOST; h += 8) {
        float m = -1e30f;
        for (int j = lane; j < H; j += 32) m = fmaxf(m, al_s[h * H + j]);
#pragma unroll
        for (int d = 16; d > 0; d >>= 1) m = fmaxf(m, __shfl_xor_sync(0xffffffffu, m, d));
        mx[h] = m;   // all lanes have m; redundant write is fine
    }
    __syncthreads();
    for (int i = t; i < NHOST * H; i += 256)
        al_s[i] = expf(al_s[i] - mx[i / H]);
    __syncthreads();
    for (int h = w; h < NHOST; h += 8) {
        float s = 0.f;
        for (int j = lane; j < H; j += 32) s += al_s[h * H + j];
#pragma unroll
        for (int d = 16; d > 0; d >>= 1) s += __shfl_xor_sync(0xffffffffu, s, d);
        rinv[h] = 1.0f / s;
    }
    __syncthreads();
    if (t < H) {
        float o = 0.f;
#pragma unroll
        for (int h = 0; h < NHOST; h++)
            o += al_s[h * H + t] * rinv[h] * __ldg(&flbuf[(size_t)(b * NHOST + h) * H + t]);
        d_cat[(size_t)b * 512 + t] = o;
    }
    // copy g into cat tail
    for (int j = t; j < H1; j += 256)
        d_cat[(size_t)b * 512 + H + j] = d_g[(size_t)b * H1 + j];
}

// ---------------- k_gup: g += cat[:KK] @ gW[KK,256] + gb -------------------
// 8 rows/block (grid 32), 256 threads: cg=t&63 (4 cols), rg=t>>6 (2 rows).
template <int KK, int HOFF>
__global__ void k_gup(const float* __restrict__ gW, const float* __restrict__ gb) {
    __shared__ float xs[64][8 + 2];
    int r0 = blockIdx.x * 8;
    int t = threadIdx.x;   // 256
    int cg = t & 63;
    int rg = t >> 6;       // 0..3 → rows rg*2, rg*2+1
    u64 acc[4];
#pragma unroll
    for (int c = 0; c < 4; c++) acc[c] = 0ull;
    for (int kc = 0; kc < KK; kc += 64) {
        __syncthreads();
        for (int i = t; i < 8 * 64; i += 256) {
            int r = i >> 6, k = i & 63;
            xs[k][r] = d_cat[(size_t)(r0 + r) * 512 + kc + k];
        }
        __syncthreads();
        for (int k = 0; k < 64; k++) {
            float4 w4 = *reinterpret_cast<const float4*>(&gW[(size_t)(kc + k) * H1 + cg * 4]);
            u64 wd[4];
            asm("mov.b64 %0, {%1, %1};" : "=l"(wd[0]) : "f"(w4.x));
            asm("mov.b64 %0, {%1, %1};" : "=l"(wd[1]) : "f"(w4.y));
            asm("mov.b64 %0, {%1, %1};" : "=l"(wd[2]) : "f"(w4.z));
            asm("mov.b64 %0, {%1, %1};" : "=l"(wd[3]) : "f"(w4.w));
            u64 xp = *reinterpret_cast<const u64*>(&xs[k][rg * 2]);
#pragma unroll
            for (int c = 0; c < 4; c++)
                asm("fma.rn.f32x2 %0, %1, %2, %0;" : "+l"(acc[c]) : "l"(xp), "l"(wd[c]));
        }
    }
    float4 b4 = *reinterpret_cast<const float4*>(&gb[cg * 4]);
    float lo[4], hi[4];
#pragma unroll
    for (int c = 0; c < 4; c++)
        asm("mov.b64 {%0, %1}, %2;" : "=f"(lo[c]), "=f"(hi[c]) : "l"(acc[c]));
    int ra = r0 + rg * 2;
    // residual: g_old lives in cat[b][HOFF + col]
    float4 ga4 = *reinterpret_cast<const float4*>(&d_cat[(size_t)ra * 512 + HOFF + cg * 4]);
    float4 gb4 = *reinterpret_cast<const float4*>(&d_cat[(size_t)(ra + 1) * 512 + HOFF + cg * 4]);
    float4 oa = make_float4(ga4.x + lo[0] + b4.x, ga4.y + lo[1] + b4.y,
                            ga4.z + lo[2] + b4.z, ga4.w + lo[3] + b4.w);
    float4 ob = make_float4(gb4.x + hi[0] + b4.x, gb4.y + hi[1] + b4.y,
                            gb4.z + hi[2] + b4.z, gb4.w + hi[3] + b4.w);
    *reinterpret_cast<float4*>(&d_g[(size_t)ra * H1 + cg * 4])       = oa;
    *reinterpret_cast<float4*>(&d_g[(size_t)(ra + 1) * H1 + cg * 4]) = ob;
}

// ---------------- final head: relu(g@o1W+o1b)@o2W + o2b -------------------
__global__ void k_head(const float* __restrict__ o1W, const float* __restrict__ o1b,
                       const float* __restrict__ o2W, const float* __restrict__ o2b,
                       float* __restrict__ out) {
    int b = blockIdx.x;
    int t = threadIdx.x; // 64
    __shared__ float gs[H1];
    for (int i = t; i < H1; i += 64) gs[i] = d_g[(size_t)b * H1 + i];
    __syncthreads();
    float a0 = o1b[t], a1 = 0.f, a2 = 0.f, a3 = 0.f;
    for (int k = 0; k < H1; k += 4) {
        a0 += gs[k]     * __ldg(&o1W[(k)     * H2 + t]);
        a1 += gs[k + 1] * __ldg(&o1W[(k + 1) * H2 + t]);
        a2 += gs[k + 2] * __ldg(&o1W[(k + 2) * H2 + t]);
        a3 += gs[k + 3] * __ldg(&o1W[(k + 3) * H2 + t]);
    }
    float acc = (a0 + a1) + (a2 + a3);
    float v = fmaxf(acc, 0.f) * __ldg(&o2W[t]);
    __shared__ float rs[64];
    rs[t] = v;
    __syncthreads();
    if (t < 32) {
        float s = rs[t] + rs[t + 32];
#pragma unroll
        for (int d = 16; d > 0; d >>= 1) s += __shfl_down_sync(0xffffffffu, s, d);
        if (t == 0) out[b] = s + o2b[0];
    }
}

// ---------------- launch ---------------------------------------------------
extern "C" void kernel_launch(void* const* d_in, const int* in_sizes, int n_in,
                              void* d_out, int out_size) {
    const float* x       = (const float*)d_in[0];
    const int*   ei      = (const int*)d_in[1];
    const int*   hostidx = (const int*)d_in[2];
    const float* W1 = (const float*)d_in[3];
    const float* b1 = (const float*)d_in[4];
    const float* W2 = (const float*)d_in[5];
    const float* b2 = (const float*)d_in[6];
    const float* a0W = (const float*)d_in[7];  const float* a0b = (const float*)d_in[8];
    const float* f0W = (const float*)d_in[9];  const float* f0b = (const float*)d_in[10];
    const float* g0W = (const float*)d_in[11]; const float* g0b = (const float*)d_in[12];
    const float* a1W = (const float*)d_in[13]; const float* a1b = (const float*)d_in[14];
    const float* f1W = (const float*)d_in[15]; const float* f1b = (const float*)d_in[16];
    const float* g1W = (const float*)d_in[17]; const float* g1b = (const float*)d_in[18];
    const float* a2W = (const float*)d_in[19]; const float* a2b = (const float*)d_in[20];
    const float* f2W = (const float*)d_in[21]; const float* f2b = (const float*)d_in[22];
    const float* g2W = (const float*)d_in[23]; const float* g2b = (const float*)d_in[24];
    const float* o1W = (const float*)d_in[25]; const float* o1b = (const float*)d_in[26];
    const float* o2W = (const float*)d_in[27]; const float* o2b = (const float*)d_in[28];
    float* out = (float*)d_out;

    const int* src = ei;
    const int* dst = ei + EE;

    float* x1_ptr;  cudaGetSymbolAddress((void**)&x1_ptr,  d_x1);
    float* x2h_ptr; cudaGetSymbolAddress((void**)&x2h_ptr, d_x2h);
    float* al_ptr;  cudaGetSymbolAddress((void**)&al_ptr,  d_al);
    float* fl_ptr;  cudaGetSymbolAddress((void**)&fl_ptr,  d_fl);

    k_zero<<<ZN / 256, 256>>>();                               // 1
    k_count_mh<<<(EE + 255) / 256, 256>>>(dst, hostidx);       // 2
    k_scan<<<1, 1024>>>();                                     // 3
    k_gemm1<<<NN / G1R, 256>>>(x, W1);                         // 4 ← profiled (retiled)
    k_fill_me<<<(EE + 255) / 256, 256>>>(src, dst);            // 5
    k_mklist<<<NN / 256, 256>>>();                             // 6

    // stage-0 attention: gathered GEMMs + softmax + g-update GEMM
    k_lin<IN_F, H1, 32><<<NR / 32, 256>>>(x, hostidx, a0W, a0b, al_ptr);  // 7
    k_lin<IN_F, H1, 32><<<NR / 32, 256>>>(x, hostidx, f0W, f0b, fl_ptr);  // 8
    k_soft<H1><<<BB, 256>>>(al_ptr, fl_ptr);                              // 9
    k_gup<H1 + H1, H1><<<BB / 8, 256>>>(g0W, g0b);                        // 10

    // layer 1
    k_agg1<<<NN, 256>>>(b1);                                              // 11
    k_lin<H1, H1, 32><<<NR / 32, 256>>>(x1_ptr, hostidx, a1W, a1b, al_ptr); // 12
    k_lin<H1, H1, 32><<<NR / 32, 256>>>(x1_ptr, hostidx, f1W, f1b, fl_ptr); // 13
    k_soft<H1><<<BB, 256>>>(al_ptr, fl_ptr);                              // 14
    k_gup<H1 + H1, H1><<<BB / 8, 256>>>(g1W, g1b);                        // 15

    // layer 2
    k_gemm2<<<(NN + G2R - 1) / G2R, 256>>>(W2);                           // 16
    k_agg2<<<NR, 64>>>(hostidx, b2);                                      // 17
    k_lin<H2, H2, 128><<<NR / 128, 256>>>(x2h_ptr, (const int*)nullptr, a2W, a2b, al_ptr); // 18
    k_lin<H2, H2, 128><<<NR / 128, 256>>>(x2h_ptr, (const int*)nullptr, f2W, f2b, fl_ptr); // 19
    k_soft<H2><<<BB, 256>>>(al_ptr, fl_ptr);                              // 20
    k_gup<H2 + H1, H2><<<BB / 8, 256>>>(g2W, g2b);                        // 21

    // head
    k_head<<<BB, 64>>>(o1W, o1b, o2W, o2b, out);                          // 22
}

// round 9
// speedup vs baseline: 1.5097x; 1.5097x over previous
#include <cuda_runtime.h>
#include <math.h>

#define NN 51200      // nodes
#define EE 409600     // edges (without self loops)
#define BB 256        // batch
#define NHOST 13
#define IN_F 64
#define H1 256
#define H2 64
#define ZN 65536      // max(NN, BB*H1) — elements to zero

typedef unsigned long long u64;

// ---------------- scratch (static device globals; no runtime alloc) -------
__device__ int   d_cnt[NN];
__device__ int   d_off[NN + 1];
__device__ int   d_cur[NN];
__device__ int   d_csr[EE];
__device__ int   d_flag[NN];
__device__ int   d_ishost[NN];
__device__ int   d_list[NN];
__device__ int   d_nf;
__device__ float d_dinv[NN];
__device__ float d_xw[(size_t)NN * H1];    // dinv * (x @ W1)
__device__ float d_x1[(size_t)NN * H1];    // relu(agg1 + b1) on frontier rows
__device__ float d_xw2[(size_t)NN * H2];   // dinv * (x1 @ W2), frontier rows only
__device__ float d_x2h[(size_t)BB * NHOST * H2];
__device__ float d_g[(size_t)BB * H1];     // global state

// ---------------- zero ------------------------------------------------------
__global__ void k_zero() {
    int i = blockIdx.x * blockDim.x + threadIdx.x;
    if (i < NN) { d_cnt[i] = 0; d_flag[i] = 0; d_ishost[i] = 0; }
    if (i < BB * H1) d_g[i] = 0.f;
    if (i == 0) d_nf = 0;
}

__global__ void k_count_mh(const int* __restrict__ dst, const int* __restrict__ hidx) {
    int e = blockIdx.x * blockDim.x + threadIdx.x;
    if (e < EE) atomicAdd(&d_cnt[dst[e]], 1);
    if (e < BB * NHOST) {
        int n = hidx[e];
        d_ishost[n] = 1;
        d_flag[n] = 1;
    }
}

// 1 block, 1024 threads, 50 items each
__global__ void k_scan() {
    __shared__ int part[1024];
    int t = threadIdx.x;
    int base = t * 50;
    int s = 0;
    for (int i = 0; i < 50; i++) s += d_cnt[base + i];
    part[t] = s;
    __syncthreads();
    for (int d = 1; d < 1024; d <<= 1) {
        int v = part[t];
        int add = (t >= d) ? part[t - d] : 0;
        __syncthreads();
        part[t] = v + add;
        __syncthreads();
    }
    int run = part[t] - s;
    for (int i = 0; i < 50; i++) {
        int c = d_cnt[base + i];
        d_off[base + i] = run;
        d_cur[base + i] = run;
        d_dinv[base + i] = rsqrtf((float)(c + 1));
        run += c;
    }
    if (t == 1023) d_off[NN] = run;
}

__global__ void k_fill_me(const int* __restrict__ src, const int* __restrict__ dst) {
    int e = blockIdx.x * blockDim.x + threadIdx.x;
    if (e < EE) {
        int d = dst[e];
        int s = src[e];
        int p = atomicAdd(&d_cur[d], 1);
        d_csr[p] = s;
        if (d_ishost[d]) d_flag[s] = 1;
    }
}

__global__ void k_mklist() {
    int i = blockIdx.x * blockDim.x + threadIdx.x;
    if (i < NN && d_flag[i]) {
        int p = atomicAdd(&d_nf, 1);
        d_list[p] = i;
    }
}

// ---------------- GEMM1: xw = dinv * (x @ W1)  [51200,64]x[64,256] ---------
#define G1R 32
__global__ void k_gemm1(const float* __restrict__ x, const float* __restrict__ W1) {
    __shared__ float xs[IN_F][G1R + 2];
    int r0 = blockIdx.x * G1R;
    int t = threadIdx.x; // 256
    int rg = t >> 6;
    int cg = t & 63;
    for (int i = t; i < G1R * IN_F; i += 256) {
        int r = i >> 6, k = i & 63;
        xs[k][r] = x[(size_t)(r0 + r) * IN_F + k];
    }
    __syncthreads();
    u64 acc[4][4];
#pragma unroll
    for (int p = 0; p < 4; p++)
#pragma unroll
        for (int c = 0; c < 4; c++) acc[p][c] = 0ull;
    for (int k = 0; k < IN_F; k++) {
        float4 w4 = *reinterpret_cast<const float4*>(&W1[k * H1 + cg * 4]);
        u64 wd[4];
        asm("mov.b64 %0, {%1, %1};" : "=l"(wd[0]) : "f"(w4.x));
        asm("mov.b64 %0, {%1, %1};" : "=l"(wd[1]) : "f"(w4.y));
        asm("mov.b64 %0, {%1, %1};" : "=l"(wd[2]) : "f"(w4.z));
        asm("mov.b64 %0, {%1, %1};" : "=l"(wd[3]) : "f"(w4.w));
        u64 xp[4];
#pragma unroll
        for (int p = 0; p < 4; p++)
            xp[p] = *reinterpret_cast<const u64*>(&xs[k][rg * 8 + 2 * p]);
#pragma unroll
        for (int p = 0; p < 4; p++)
#pragma unroll
            for (int c = 0; c < 4; c++)
                asm("fma.rn.f32x2 %0, %1, %2, %0;" : "+l"(acc[p][c]) : "l"(xp[p]), "l"(wd[c]));
    }
#pragma unroll
    for (int p = 0; p < 4; p++) {
        float lo[4], hi[4];
#pragma unroll
        for (int c = 0; c < 4; c++)
            asm("mov.b64 {%0, %1}, %2;" : "=f"(lo[c]), "=f"(hi[c]) : "l"(acc[p][c]));
        int ra = r0 + rg * 8 + 2 * p;
        float da = d_dinv[ra], db = d_dinv[ra + 1];
        float4 oa = make_float4(da * lo[0], da * lo[1], da * lo[2], da * lo[3]);
        float4 ob = make_float4(db * hi[0], db * hi[1], db * hi[2], db * hi[3]);
        *reinterpret_cast<float4*>(&d_xw[(size_t)ra * H1 + cg * 4])       = oa;
        *reinterpret_cast<float4*>(&d_xw[(size_t)(ra + 1) * H1 + cg * 4]) = ob;
    }
}

// ---------------- layer-1 max aggregation (frontier list) ------------------
__global__ void k_agg1(const float* __restrict__ b1) {
    int bi = blockIdx.x;
    if (bi >= d_nf) return;
    int i = d_list[bi];
    int t = threadIdx.x; // 256
    __shared__ int nbr[256];
    float m = d_xw[(size_t)i * H1 + t];
    int e0 = d_off[i], e1 = d_off[i + 1];
    for (int base = e0; base < e1; base += 256) {
        int n = min(256, e1 - base);
        __syncthreads();
        if (t < n) nbr[t] = d_csr[base + t];
        __syncthreads();
        int e = 0;
        for (; e + 4 <= n; e += 4) {
            int s0 = nbr[e], s1 = nbr[e + 1], s2 = nbr[e + 2], s3 = nbr[e + 3];
            float v0 = __ldg(&d_xw[(size_t)s0 * H1 + t]);
            float v1 = __ldg(&d_xw[(size_t)s1 * H1 + t]);
            float v2 = __ldg(&d_xw[(size_t)s2 * H1 + t]);
            float v3 = __ldg(&d_xw[(size_t)s3 * H1 + t]);
            m = fmaxf(m, fmaxf(fmaxf(v0, v1), fmaxf(v2, v3)));
        }
        for (; e < n; e++)
            m = fmaxf(m, __ldg(&d_xw[(size_t)nbr[e] * H1 + t]));
    }
    d_x1[(size_t)i * H1 + t] = fmaxf(d_dinv[i] * m + b1[t], 0.f);
}

// ---------------- GEMM2 on frontier rows: xw2 = dinv * (x1 @ W2) -----------
#define G2R 128
__global__ void k_gemm2(const float* __restrict__ W2) {
    int r0 = blockIdx.x * G2R;
    int nf = d_nf;
    if (r0 >= nf) return;
    __shared__ float xs[64][G2R + 2];
    __shared__ int rows[G2R];
    int t = threadIdx.x;      // 256
    int rg = t >> 4;
    int cg = t & 15;
    if (t < G2R) rows[t] = d_list[min(r0 + t, nf - 1)];
    __syncthreads();
    u64 acc[4][4];
#pragma unroll
    for (int p = 0; p < 4; p++)
#pragma unroll
        for (int c = 0; c < 4; c++) acc[p][c] = 0ull;
    for (int kc = 0; kc < H1; kc += 64) {
        __syncthreads();
        for (int i = t; i < G2R * 64; i += 256) {
            int r = i >> 6, k = i & 63;
            xs[k][r] = d_x1[(size_t)rows[r] * H1 + kc + k];
        }
        __syncthreads();
        for (int k = 0; k < 64; k++) {
            float4 w4 = *reinterpret_cast<const float4*>(&W2[(kc + k) * H2 + cg * 4]);
            u64 wd[4];
            asm("mov.b64 %0, {%1, %1};" : "=l"(wd[0]) : "f"(w4.x));
            asm("mov.b64 %0, {%1, %1};" : "=l"(wd[1]) : "f"(w4.y));
            asm("mov.b64 %0, {%1, %1};" : "=l"(wd[2]) : "f"(w4.z));
            asm("mov.b64 %0, {%1, %1};" : "=l"(wd[3]) : "f"(w4.w));
            u64 xp[4];
#pragma unroll
            for (int p = 0; p < 4; p++)
                xp[p] = *reinterpret_cast<const u64*>(&xs[k][rg * 8 + 2 * p]);
#pragma unroll
            for (int p = 0; p < 4; p++)
#pragma unroll
                for (int c = 0; c < 4; c++)
                    asm("fma.rn.f32x2 %0, %1, %2, %0;" : "+l"(acc[p][c]) : "l"(xp[p]), "l"(wd[c]));
        }
    }
#pragma unroll
    for (int p = 0; p < 4; p++) {
        float lo[4], hi[4];
#pragma unroll
        for (int c = 0; c < 4; c++)
            asm("mov.b64 {%0, %1}, %2;" : "=f"(lo[c]), "=f"(hi[c]) : "l"(acc[p][c]));
        int rla = rg * 8 + 2 * p;
        int ga = rows[rla], gb2 = rows[rla + 1];
        float da = d_dinv[ga], db = d_dinv[gb2];
        float4 oa = make_float4(da * lo[0], da * lo[1], da * lo[2], da * lo[3]);
        float4 ob = make_float4(db * hi[0], db * hi[1], db * hi[2], db * hi[3]);
        *reinterpret_cast<float4*>(&d_xw2[(size_t)ga * H2 + cg * 4])  = oa;
        *reinterpret_cast<float4*>(&d_xw2[(size_t)gb2 * H2 + cg * 4]) = ob;
    }
}

// ---------------- layer-2 max aggregation (HOST nodes only) ---------------
__global__ void k_agg2(const int* __restrict__ hidx, const float* __restrict__ b2) {
    int hi = blockIdx.x;
    int t = threadIdx.x;       // 64
    __shared__ int nbr[64];
    int node = hidx[hi];
    float m = d_xw2[(size_t)node * H2 + t];
    int e0 = d_off[node], e1 = d_off[node + 1];
    for (int base = e0; base < e1; base += 64) {
        int n = min(64, e1 - base);
        __syncthreads();
        if (t < n) nbr[t] = d_csr[base + t];
        __syncthreads();
        int e = 0;
        for (; e + 4 <= n; e += 4) {
            int s0 = nbr[e], s1 = nbr[e + 1], s2 = nbr[e + 2], s3 = nbr[e + 3];
            float v0 = __ldg(&d_xw2[(size_t)s0 * H2 + t]);
            float v1 = __ldg(&d_xw2[(size_t)s1 * H2 + t]);
            float v2 = __ldg(&d_xw2[(size_t)s2 * H2 + t]);
            float v3 = __ldg(&d_xw2[(size_t)s3 * H2 + t]);
            m = fmaxf(m, fmaxf(fmaxf(v0, v1), fmaxf(v2, v3)));
        }
        for (; e < n; e++)
            m = fmaxf(m, __ldg(&d_xw2[(size_t)nbr[e] * H2 + t]));
    }
    d_x2h[(size_t)hi * H2 + t] = fmaxf(d_dinv[node] * m + b2[t], 0.f);
}

// ---------------- self attention — 512 threads, a/f split ------------------
// Phase A keeps r6's 13-host-ILP loop verbatim, but the att-matvec runs on
// threads [0,256) and the feat-matvec on threads [256,512) → 2× warps,
// half the live registers (13 accs not 26), identical ILP structure.
template <int F, int H>
__global__ __launch_bounds__(512) void k_attn(
        const float* __restrict__ v, const int* __restrict__ hidx,
        const float* __restrict__ aW, const float* __restrict__ ab,
        const float* __restrict__ fW, const float* __restrict__ fb,
        const float* __restrict__ gW, const float* __restrict__ gb) {
    constexpr int KK = H + H1;
    int b = blockIdx.x;
    int tid = threadIdx.x;               // 512
    int half = tid >> 8;                 // 0: att, 1: feat
    int t = tid & 255;
    int lane = tid & 31, w = tid >> 5;   // 16 warps

    __shared__ float vs[NHOST * F];
    __shared__ float ls[NHOST * H];      // att logits → exp
    __shared__ float fs[NHOST * H];      // feat
    __shared__ float cat[KK];            // [out | g]
    __shared__ float pd[2][H1];
    __shared__ float gs[H1];
    __shared__ float mx[NHOST], rinv[NHOST];

    for (int i = tid; i < NHOST * F; i += 512) {
        int h = i / F, f = i % F;
        int row = hidx ? hidx[b * NHOST + h] : (b * NHOST + h);
        vs[i] = v[(size_t)row * F + f];
    }
    if (tid < H1) gs[tid] = d_g[(size_t)b * H1 + tid];
    __syncthreads();

    // Phase A — r6 loop structure, one matrix per 256-thread half
    if (t < H) {
        const float* W  = half ? fW : aW;
        const float* bb = half ? fb : ab;
        float* outb     = half ? fs : ls;
        float aL[NHOST];
#pragma unroll
        for (int h = 0; h < NHOST; h++) aL[h] = 0.f;
        for (int f = 0; f < F; f++) {
            float wv = __ldg(&W[f * H + t]);
#pragma unroll
            for (int h = 0; h < NHOST; h++)
                aL[h] += vs[h * F + f] * wv;
        }
        float bv = __ldg(&bb[t]);
#pragma unroll
        for (int h = 0; h < NHOST; h++) outb[h * H + t] = aL[h] + bv;
    }
    __syncthreads();

    // B1: per-host max (warp w ↔ host w; 16 warps ≥ 13 hosts)
    if (w < NHOST) {
        float m = -1e30f;
        for (int j = lane; j < H; j += 32) m = fmaxf(m, ls[w * H + j]);
#pragma unroll
        for (int d = 16; d > 0; d >>= 1) m = fmaxf(m, __shfl_xor_sync(0xffffffffu, m, d));
        if (lane == 0) mx[w] = m;
    }
    __syncthreads();
    // B2: exp
    for (int i = tid; i < NHOST * H; i += 512) ls[i] = expf(ls[i] - mx[i / H]);
    __syncthreads();
    // B3: per-host sum
    if (w < NHOST) {
        float s = 0.f;
        for (int j = lane; j < H; j += 32) s += ls[w * H + j];
#pragma unroll
        for (int d = 16; d > 0; d >>= 1) s += __shfl_xor_sync(0xffffffffu, s, d);
        if (lane == 0) rinv[w] = 1.0f / s;
    }
    __syncthreads();

    // Phase C: out + copy g into cat
    if (tid < H) {
        float o = 0.f;
#pragma unroll
        for (int h = 0; h < NHOST; h++)
            o += ls[h * H + tid] * rinv[h] * fs[h * H + tid];
        cat[tid] = o;
    }
    for (int j = tid; j < H1; j += 512) cat[H + j] = gs[j];
    __syncthreads();

    // Phase D: matvec cat[KK] @ gW[KK,H1] split over 2 k-partitions, 4 accs
    {
        constexpr int CH = KK / 2;
        int k0 = half * CH;
        float a0 = 0.f, a1 = 0.f, a2 = 0.f, a3 = 0.f;
        for (int k = k0; k < k0 + CH; k += 4) {
            a0 += cat[k]     * __ldg(&gW[(k)     * H1 + t]);
            a1 += cat[k + 1] * __ldg(&gW[(k + 1) * H1 + t]);
            a2 += cat[k + 2] * __ldg(&gW[(k + 2) * H1 + t]);
            a3 += cat[k + 3] * __ldg(&gW[(k + 3) * H1 + t]);
        }
        pd[half][t] = (a0 + a1) + (a2 + a3);
    }
    __syncthreads();
    if (tid < H1)
        d_g[(size_t)b * H1 + tid] = gs[tid] + __ldg(&gb[tid]) + pd[0][tid] + pd[1][tid];
}

// ---------------- final head: relu(g@o1W+o1b)@o2W + o2b -------------------
__global__ void k_head(const float* __restrict__ o1W, const float* __restrict__ o1b,
                       const float* __restrict__ o2W, const float* __restrict__ o2b,
                       float* __restrict__ out) {
    int b = blockIdx.x;
    int t = threadIdx.x; // 64
    __shared__ float gs[H1];
    for (int i = t; i < H1; i += 64) gs[i] = d_g[(size_t)b * H1 + i];
    __syncthreads();
    float a0 = o1b[t], a1 = 0.f, a2 = 0.f, a3 = 0.f;
    for (int k = 0; k < H1; k += 4) {
        a0 += gs[k]     * __ldg(&o1W[(k)     * H2 + t]);
        a1 += gs[k + 1] * __ldg(&o1W[(k + 1) * H2 + t]);
        a2 += gs[k + 2] * __ldg(&o1W[(k + 2) * H2 + t]);
        a3 += gs[k + 3] * __ldg(&o1W[(k + 3) * H2 + t]);
    }
    float acc = (a0 + a1) + (a2 + a3);
    float v = fmaxf(acc, 0.f) * __ldg(&o2W[t]);
    __shared__ float rs[64];
    rs[t] = v;
    __syncthreads();
    if (t < 32) {
        float s = rs[t] + rs[t + 32];
#pragma unroll
        for (int d = 16; d > 0; d >>= 1) s += __shfl_down_sync(0xffffffffu, s, d);
        if (t == 0) out[b] = s + o2b[0];
    }
}

// ---------------- launch ---------------------------------------------------
extern "C" void kernel_launch(void* const* d_in, const int* in_sizes, int n_in,
                              void* d_out, int out_size) {
    const float* x       = (const float*)d_in[0];
    const int*   ei      = (const int*)d_in[1];
    const int*   hostidx = (const int*)d_in[2];
    const float* W1 = (const float*)d_in[3];
    const float* b1 = (const float*)d_in[4];
    const float* W2 = (const float*)d_in[5];
    const float* b2 = (const float*)d_in[6];
    const float* a0W = (const float*)d_in[7];  const float* a0b = (const float*)d_in[8];
    const float* f0W = (const float*)d_in[9];  const float* f0b = (const float*)d_in[10];
    const float* g0W = (const float*)d_in[11]; const float* g0b = (const float*)d_in[12];
    const float* a1W = (const float*)d_in[13]; const float* a1b = (const float*)d_in[14];
    const float* f1W = (const float*)d_in[15]; const float* f1b = (const float*)d_in[16];
    const float* g1W = (const float*)d_in[17]; const float* g1b = (const float*)d_in[18];
    const float* a2W = (const float*)d_in[19]; const float* a2b = (const float*)d_in[20];
    const float* f2W = (const float*)d_in[21]; const float* f2b = (const float*)d_in[22];
    const float* g2W = (const float*)d_in[23]; const float* g2b = (const float*)d_in[24];
    const float* o1W = (const float*)d_in[25]; const float* o1b = (const float*)d_in[26];
    const float* o2W = (const float*)d_in[27]; const float* o2b = (const float*)d_in[28];
    float* out = (float*)d_out;

    const int* src = ei;
    const int* dst = ei + EE;

    float* x1_ptr;  cudaGetSymbolAddress((void**)&x1_ptr,  d_x1);
    float* x2h_ptr; cudaGetSymbolAddress((void**)&x2h_ptr, d_x2h);

    k_zero<<<ZN / 256, 256>>>();                               // 1
    k_count_mh<<<(EE + 255) / 256, 256>>>(dst, hostidx);       // 2
    k_scan<<<1, 1024>>>();                                     // 3
    // stage-0 attention — slot 4 → profiled (new split-half version)
    k_attn<IN_F, H1><<<BB, 512>>>(x, hostidx, a0W, a0b, f0W, f0b, g0W, g0b);    // 4
    k_gemm1<<<NN / G1R, 256>>>(x, W1);                         // 5
    k_fill_me<<<(EE + 255) / 256, 256>>>(src, dst);            // 6
    k_mklist<<<NN / 256, 256>>>();                             // 7

    // layer 1
    k_agg1<<<NN, 256>>>(b1);                                   // 8
    k_attn<H1, H1><<<BB, 512>>>(x1_ptr, hostidx, a1W, a1b, f1W, f1b, g1W, g1b); // 9

    // layer 2
    k_gemm2<<<(NN + G2R - 1) / G2R, 256>>>(W2);                // 10
    k_agg2<<<BB * NHOST, 64>>>(hostidx, b2);                   // 11
    k_attn<H2, H2><<<BB, 512>>>(x2h_ptr, (const int*)nullptr, a2W, a2b, f2W, f2b, g2W, g2b); // 12

    // head
    k_head<<<BB, 64>>>(o1W, o1b, o2W, o2b, out);               // 13
}

// round 10
// speedup vs baseline: 1.9652x; 1.3017x over previous
#include <cuda_runtime.h>
#include <math.h>

#define NN 51200      // nodes
#define EE 409600     // edges (without self loops)
#define BB 256        // batch
#define NHOST 13
#define IN_F 64
#define H1 256
#define H2 64
#define ZN 65536      // max(NN, BB*H1) — elements to zero

typedef unsigned long long u64;

// ---------------- scratch (static device globals; no runtime alloc) -------
__device__ int   d_cnt[NN];
__device__ int   d_off[NN + 1];
__device__ int   d_cur[NN];
__device__ int   d_csr[EE];
__device__ int   d_flag[NN];
__device__ int   d_ishost[NN];
__device__ int   d_list[NN];
__device__ int   d_nf;
__device__ float d_dinv[NN];
__device__ float d_xw[(size_t)NN * H1];    // dinv * (x @ W1)
__device__ float d_x1[(size_t)NN * H1];    // relu(agg1 + b1) on frontier rows
__device__ float d_xw2[(size_t)NN * H2];   // dinv * (x1 @ W2), frontier rows only
__device__ float d_x2h[(size_t)BB * NHOST * H2];
__device__ float d_g[(size_t)BB * H1];     // global state

// ---------------- zero ------------------------------------------------------
__global__ void k_zero() {
    int i = blockIdx.x * blockDim.x + threadIdx.x;
    if (i < NN) { d_cnt[i] = 0; d_flag[i] = 0; d_ishost[i] = 0; }
    if (i < BB * H1) d_g[i] = 0.f;
    if (i == 0) d_nf = 0;
}

__global__ void k_count_mh(const int* __restrict__ dst, const int* __restrict__ hidx) {
    int e = blockIdx.x * blockDim.x + threadIdx.x;
    if (e < EE) atomicAdd(&d_cnt[dst[e]], 1);
    if (e < BB * NHOST) {
        int n = hidx[e];
        d_ishost[n] = 1;
        d_flag[n] = 1;
    }
}

// 1 block, 1024 threads, 50 items each
__global__ void k_scan() {
    __shared__ int part[1024];
    int t = threadIdx.x;
    int base = t * 50;
    int s = 0;
    for (int i = 0; i < 50; i++) s += d_cnt[base + i];
    part[t] = s;
    __syncthreads();
    for (int d = 1; d < 1024; d <<= 1) {
        int v = part[t];
        int add = (t >= d) ? part[t - d] : 0;
        __syncthreads();
        part[t] = v + add;
        __syncthreads();
    }
    int run = part[t] - s;
    for (int i = 0; i < 50; i++) {
        int c = d_cnt[base + i];
        d_off[base + i] = run;
        d_cur[base + i] = run;
        d_dinv[base + i] = rsqrtf((float)(c + 1));
        run += c;
    }
    if (t == 1023) d_off[NN] = run;
}

__global__ void k_fill_me(const int* __restrict__ src, const int* __restrict__ dst) {
    int e = blockIdx.x * blockDim.x + threadIdx.x;
    if (e < EE) {
        int d = dst[e];
        int s = src[e];
        int p = atomicAdd(&d_cur[d], 1);
        d_csr[p] = s;
        if (d_ishost[d]) d_flag[s] = 1;
    }
}

__global__ void k_mklist() {
    int i = blockIdx.x * blockDim.x + threadIdx.x;
    if (i < NN && d_flag[i]) {
        int p = atomicAdd(&d_nf, 1);
        d_list[p] = i;
    }
}

// ---------------- GEMM1: xw = dinv * (x @ W1)  [51200,64]x[64,256] ---------
#define G1R 32
__global__ void k_gemm1(const float* __restrict__ x, const float* __restrict__ W1) {
    __shared__ float xs[IN_F][G1R + 2];
    int r0 = blockIdx.x * G1R;
    int t = threadIdx.x; // 256
    int rg = t >> 6;
    int cg = t & 63;
    for (int i = t; i < G1R * IN_F; i += 256) {
        int r = i >> 6, k = i & 63;
        xs[k][r] = x[(size_t)(r0 + r) * IN_F + k];
    }
    __syncthreads();
    u64 acc[4][4];
#pragma unroll
    for (int p = 0; p < 4; p++)
#pragma unroll
        for (int c = 0; c < 4; c++) acc[p][c] = 0ull;
    for (int k = 0; k < IN_F; k++) {
        float4 w4 = *reinterpret_cast<const float4*>(&W1[k * H1 + cg * 4]);
        u64 wd[4];
        asm("mov.b64 %0, {%1, %1};" : "=l"(wd[0]) : "f"(w4.x));
        asm("mov.b64 %0, {%1, %1};" : "=l"(wd[1]) : "f"(w4.y));
        asm("mov.b64 %0, {%1, %1};" : "=l"(wd[2]) : "f"(w4.z));
        asm("mov.b64 %0, {%1, %1};" : "=l"(wd[3]) : "f"(w4.w));
        u64 xp[4];
#pragma unroll
        for (int p = 0; p < 4; p++)
            xp[p] = *reinterpret_cast<const u64*>(&xs[k][rg * 8 + 2 * p]);
#pragma unroll
        for (int p = 0; p < 4; p++)
#pragma unroll
            for (int c = 0; c < 4; c++)
                asm("fma.rn.f32x2 %0, %1, %2, %0;" : "+l"(acc[p][c]) : "l"(xp[p]), "l"(wd[c]));
    }
#pragma unroll
    for (int p = 0; p < 4; p++) {
        float lo[4], hi[4];
#pragma unroll
        for (int c = 0; c < 4; c++)
            asm("mov.b64 {%0, %1}, %2;" : "=f"(lo[c]), "=f"(hi[c]) : "l"(acc[p][c]));
        int ra = r0 + rg * 8 + 2 * p;
        float da = d_dinv[ra], db = d_dinv[ra + 1];
        float4 oa = make_float4(da * lo[0], da * lo[1], da * lo[2], da * lo[3]);
        float4 ob = make_float4(db * hi[0], db * hi[1], db * hi[2], db * hi[3]);
        *reinterpret_cast<float4*>(&d_xw[(size_t)ra * H1 + cg * 4])       = oa;
        *reinterpret_cast<float4*>(&d_xw[(size_t)(ra + 1) * H1 + cg * 4]) = ob;
    }
}

// ---------------- layer-1 max aggregation (frontier list) ------------------
__global__ void k_agg1(const float* __restrict__ b1) {
    int bi = blockIdx.x;
    if (bi >= d_nf) return;
    int i = d_list[bi];
    int t = threadIdx.x; // 256
    __shared__ int nbr[256];
    float m = d_xw[(size_t)i * H1 + t];
    int e0 = d_off[i], e1 = d_off[i + 1];
    for (int base = e0; base < e1; base += 256) {
        int n = min(256, e1 - base);
        __syncthreads();
        if (t < n) nbr[t] = d_csr[base + t];
        __syncthreads();
        int e = 0;
        for (; e + 4 <= n; e += 4) {
            int s0 = nbr[e], s1 = nbr[e + 1], s2 = nbr[e + 2], s3 = nbr[e + 3];
            float v0 = __ldg(&d_xw[(size_t)s0 * H1 + t]);
            float v1 = __ldg(&d_xw[(size_t)s1 * H1 + t]);
            float v2 = __ldg(&d_xw[(size_t)s2 * H1 + t]);
            float v3 = __ldg(&d_xw[(size_t)s3 * H1 + t]);
            m = fmaxf(m, fmaxf(fmaxf(v0, v1), fmaxf(v2, v3)));
        }
        for (; e < n; e++)
            m = fmaxf(m, __ldg(&d_xw[(size_t)nbr[e] * H1 + t]));
    }
    d_x1[(size_t)i * H1 + t] = fmaxf(d_dinv[i] * m + b1[t], 0.f);
}

// ---------------- GEMM2 on frontier rows: xw2 = dinv * (x1 @ W2) -----------
#define G2R 128
__global__ void k_gemm2(const float* __restrict__ W2) {
    int r0 = blockIdx.x * G2R;
    int nf = d_nf;
    if (r0 >= nf) return;
    __shared__ float xs[64][G2R + 2];
    __shared__ int rows[G2R];
    int t = threadIdx.x;      // 256
    int rg = t >> 4;
    int cg = t & 15;
    if (t < G2R) rows[t] = d_list[min(r0 + t, nf - 1)];
    __syncthreads();
    u64 acc[4][4];
#pragma unroll
    for (int p = 0; p < 4; p++)
#pragma unroll
        for (int c = 0; c < 4; c++) acc[p][c] = 0ull;
    for (int kc = 0; kc < H1; kc += 64) {
        __syncthreads();
        for (int i = t; i < G2R * 64; i += 256) {
            int r = i >> 6, k = i & 63;
            xs[k][r] = d_x1[(size_t)rows[r] * H1 + kc + k];
        }
        __syncthreads();
        for (int k = 0; k < 64; k++) {
            float4 w4 = *reinterpret_cast<const float4*>(&W2[(kc + k) * H2 + cg * 4]);
            u64 wd[4];
            asm("mov.b64 %0, {%1, %1};" : "=l"(wd[0]) : "f"(w4.x));
            asm("mov.b64 %0, {%1, %1};" : "=l"(wd[1]) : "f"(w4.y));
            asm("mov.b64 %0, {%1, %1};" : "=l"(wd[2]) : "f"(w4.z));
            asm("mov.b64 %0, {%1, %1};" : "=l"(wd[3]) : "f"(w4.w));
            u64 xp[4];
#pragma unroll
            for (int p = 0; p < 4; p++)
                xp[p] = *reinterpret_cast<const u64*>(&xs[k][rg * 8 + 2 * p]);
#pragma unroll
            for (int p = 0; p < 4; p++)
#pragma unroll
                for (int c = 0; c < 4; c++)
                    asm("fma.rn.f32x2 %0, %1, %2, %0;" : "+l"(acc[p][c]) : "l"(xp[p]), "l"(wd[c]));
        }
    }
#pragma unroll
    for (int p = 0; p < 4; p++) {
        float lo[4], hi[4];
#pragma unroll
        for (int c = 0; c < 4; c++)
            asm("mov.b64 {%0, %1}, %2;" : "=f"(lo[c]), "=f"(hi[c]) : "l"(acc[p][c]));
        int rla = rg * 8 + 2 * p;
        int ga = rows[rla], gb2 = rows[rla + 1];
        float da = d_dinv[ga], db = d_dinv[gb2];
        float4 oa = make_float4(da * lo[0], da * lo[1], da * lo[2], da * lo[3]);
        float4 ob = make_float4(db * hi[0], db * hi[1], db * hi[2], db * hi[3]);
        *reinterpret_cast<float4*>(&d_xw2[(size_t)ga * H2 + cg * 4])  = oa;
        *reinterpret_cast<float4*>(&d_xw2[(size_t)gb2 * H2 + cg * 4]) = ob;
    }
}

// ---------------- layer-2 max aggregation (HOST nodes only) ---------------
__global__ void k_agg2(const int* __restrict__ hidx, const float* __restrict__ b2) {
    int hi = blockIdx.x;
    int t = threadIdx.x;       // 64
    __shared__ int nbr[64];
    int node = hidx[hi];
    float m = d_xw2[(size_t)node * H2 + t];
    int e0 = d_off[node], e1 = d_off[node + 1];
    for (int base = e0; base < e1; base += 64) {
        int n = min(64, e1 - base);
        __syncthreads();
        if (t < n) nbr[t] = d_csr[base + t];
        __syncthreads();
        int e = 0;
        for (; e + 4 <= n; e += 4) {
            int s0 = nbr[e], s1 = nbr[e + 1], s2 = nbr[e + 2], s3 = nbr[e + 3];
            float v0 = __ldg(&d_xw2[(size_t)s0 * H2 + t]);
            float v1 = __ldg(&d_xw2[(size_t)s1 * H2 + t]);
            float v2 = __ldg(&d_xw2[(size_t)s2 * H2 + t]);
            float v3 = __ldg(&d_xw2[(size_t)s3 * H2 + t]);
            m = fmaxf(m, fmaxf(fmaxf(v0, v1), fmaxf(v2, v3)));
        }
        for (; e < n; e++)
            m = fmaxf(m, __ldg(&d_xw2[(size_t)nbr[e] * H2 + t]));
    }
    d_x2h[(size_t)hi * H2 + t] = fmaxf(d_dinv[node] * m + b2[t], 0.f);
}

// ---------------- self attention — r6 skeleton (256 thr), f32x2 phase A ----
// vsT[f][14]: hosts transposed, host 13 zero-padded so pairs load as LDS.64.
template <int F, int H>
__global__ void k_attn(const float* __restrict__ v, const int* __restrict__ hidx,
                       const float* __restrict__ aW, const float* __restrict__ ab,
                       const float* __restrict__ fW, const float* __restrict__ fb,
                       const float* __restrict__ gW, const float* __restrict__ gb) {
    int b = blockIdx.x;
    int t = threadIdx.x;           // 256
    int lane = t & 31, w = t >> 5; // 8 warps

    __shared__ float vsT[F][14];
    __shared__ float ls[NHOST * H];
    __shared__ float fs[NHOST * H];
    __shared__ float mx[NHOST], rinv[NHOST];
    __shared__ float outs[H];
    __shared__ float gs[H1];

    for (int i = t; i < NHOST * F; i += 256) {
        int h = i / F, f = i % F;
        int row = hidx ? hidx[b * NHOST + h] : (b * NHOST + h);
        vsT[f][h] = v[(size_t)row * F + f];
    }
    for (int f = t; f < F; f += 256) vsT[f][13] = 0.f;
    gs[t] = d_g[(size_t)b * H1 + t];
    __syncthreads();

    // Phase A: aL/fV for 13 hosts, packed as 7 f32x2 pairs
    if (t < H) {
        u64 aLp[7], fVp[7];
#pragma unroll
        for (int p = 0; p < 7; p++) { aLp[p] = 0ull; fVp[p] = 0ull; }
        for (int f = 0; f < F; f++) {
            float wa = __ldg(&aW[f * H + t]);
            float wf = __ldg(&fW[f * H + t]);
            u64 wa2, wf2;
            asm("mov.b64 %0, {%1, %1};" : "=l"(wa2) : "f"(wa));
            asm("mov.b64 %0, {%1, %1};" : "=l"(wf2) : "f"(wf));
#pragma unroll
            for (int p = 0; p < 7; p++) {
                u64 xv = *reinterpret_cast<const u64*>(&vsT[f][2 * p]);
                asm("fma.rn.f32x2 %0, %1, %2, %0;" : "+l"(aLp[p]) : "l"(xv), "l"(wa2));
                asm("fma.rn.f32x2 %0, %1, %2, %0;" : "+l"(fVp[p]) : "l"(xv), "l"(wf2));
            }
        }
        float abv = __ldg(&ab[t]), fbv = __ldg(&fb[t]);
#pragma unroll
        for (int p = 0; p < 7; p++) {
            float alo, ahi, flo, fhi;
            asm("mov.b64 {%0, %1}, %2;" : "=f"(alo), "=f"(ahi) : "l"(aLp[p]));
            asm("mov.b64 {%0, %1}, %2;" : "=f"(flo), "=f"(fhi) : "l"(fVp[p]));
            ls[(2 * p) * H + t] = alo + abv;
            fs[(2 * p) * H + t] = flo + fbv;
            if (2 * p + 1 < NHOST) {
                ls[(2 * p + 1) * H + t] = ahi + abv;
                fs[(2 * p + 1) * H + t] = fhi + fbv;
            }
        }
    }
    __syncthreads();

    // Phase B1: per-host max via warp reductions
    for (int h = w; h < NHOST; h += 8) {
        float m = -1e30f;
        for (int j = lane; j < H; j += 32) m = fmaxf(m, ls[h * H + j]);
#pragma unroll
        for (int d = 16; d > 0; d >>= 1) m = fmaxf(m, __shfl_xor_sync(0xffffffffu, m, d));
        if (lane == 0) mx[h] = m;
    }
    __syncthreads();
    // Phase B2: exp
    for (int i = t; i < NHOST * H; i += 256) ls[i] = expf(ls[i] - mx[i / H]);
    __syncthreads();
    // Phase B3: per-host sum via warp reductions
    for (int h = w; h < NHOST; h += 8) {
        float s = 0.f;
        for (int j = lane; j < H; j += 32) s += ls[h * H + j];
#pragma unroll
        for (int d = 16; d > 0; d >>= 1) s += __shfl_xor_sync(0xffffffffu, s, d);
        if (lane == 0) rinv[h] = 1.0f / s;
    }
    __syncthreads();

    // Phase C: weighted sum over hosts
    if (t < H) {
        float o = 0.f;
#pragma unroll
        for (int h = 0; h < NHOST; h++)
            o += ls[h * H + t] * rinv[h] * fs[h * H + t];
        outs[t] = o;
    }
    __syncthreads();

    // Phase D: g_new = concat(out,g) @ gW + gb ; g += g_new  (4 indep accs)
    float a0 = __ldg(&gb[t]), a1 = 0.f, a2 = 0.f, a3 = 0.f;
    for (int k = 0; k < H; k += 4) {
        a0 += outs[k]     * __ldg(&gW[(k)     * H1 + t]);
        a1 += outs[k + 1] * __ldg(&gW[(k + 1) * H1 + t]);
        a2 += outs[k + 2] * __ldg(&gW[(k + 2) * H1 + t]);
        a3 += outs[k + 3] * __ldg(&gW[(k + 3) * H1 + t]);
    }
    for (int k = 0; k < H1; k += 4) {
        a0 += gs[k]     * __ldg(&gW[(H + k)     * H1 + t]);
        a1 += gs[k + 1] * __ldg(&gW[(H + k + 1) * H1 + t]);
        a2 += gs[k + 2] * __ldg(&gW[(H + k + 2) * H1 + t]);
        a3 += gs[k + 3] * __ldg(&gW[(H + k + 3) * H1 + t]);
    }
    d_g[(size_t)b * H1 + t] = gs[t] + (a0 + a1) + (a2 + a3);
}

// ---------------- final head: relu(g@o1W+o1b)@o2W + o2b -------------------
__global__ void k_head(const float* __restrict__ o1W, const float* __restrict__ o1b,
                       const float* __restrict__ o2W, const float* __restrict__ o2b,
                       float* __restrict__ out) {
    int b = blockIdx.x;
    int t = threadIdx.x; // 64
    __shared__ float gs[H1];
    for (int i = t; i < H1; i += 64) gs[i] = d_g[(size_t)b * H1 + i];
    __syncthreads();
    float a0 = o1b[t], a1 = 0.f, a2 = 0.f, a3 = 0.f;
    for (int k = 0; k < H1; k += 4) {
        a0 += gs[k]     * __ldg(&o1W[(k)     * H2 + t]);
        a1 += gs[k + 1] * __ldg(&o1W[(k + 1) * H2 + t]);
        a2 += gs[k + 2] * __ldg(&o1W[(k + 2) * H2 + t]);
        a3 += gs[k + 3] * __ldg(&o1W[(k + 3) * H2 + t]);
    }
    float acc = (a0 + a1) + (a2 + a3);
    float v = fmaxf(acc, 0.f) * __ldg(&o2W[t]);
    __shared__ float rs[64];
    rs[t] = v;
    __syncthreads();
    if (t < 32) {
        float s = rs[t] + rs[t + 32];
#pragma unroll
        for (int d = 16; d > 0; d >>= 1) s += __shfl_down_sync(0xffffffffu, s, d);
        if (t == 0) out[b] = s + o2b[0];
    }
}

// ---------------- launch ---------------------------------------------------
extern "C" void kernel_launch(void* const* d_in, const int* in_sizes, int n_in,
                              void* d_out, int out_size) {
    const float* x       = (const float*)d_in[0];
    const int*   ei      = (const int*)d_in[1];
    const int*   hostidx = (const int*)d_in[2];
    const float* W1 = (const float*)d_in[3];
    const float* b1 = (const float*)d_in[4];
    const float* W2 = (const float*)d_in[5];
    const float* b2 = (const float*)d_in[6];
    const float* a0W = (const float*)d_in[7];  const float* a0b = (const float*)d_in[8];
    const float* f0W = (const float*)d_in[9];  const float* f0b = (const float*)d_in[10];
    const float* g0W = (const float*)d_in[11]; const float* g0b = (const float*)d_in[12];
    const float* a1W = (const float*)d_in[13]; const float* a1b = (const float*)d_in[14];
    const float* f1W = (const float*)d_in[15]; const float* f1b = (const float*)d_in[16];
    const float* g1W = (const float*)d_in[17]; const float* g1b = (const float*)d_in[18];
    const float* a2W = (const float*)d_in[19]; const float* a2b = (const float*)d_in[20];
    const float* f2W = (const float*)d_in[21]; const float* f2b = (const float*)d_in[22];
    const float* g2W = (const float*)d_in[23]; const float* g2b = (const float*)d_in[24];
    const float* o1W = (const float*)d_in[25]; const float* o1b = (const float*)d_in[26];
    const float* o2W = (const float*)d_in[27]; const float* o2b = (const float*)d_in[28];
    float* out = (float*)d_out;

    const int* src = ei;
    const int* dst = ei + EE;

    float* x1_ptr;  cudaGetSymbolAddress((void**)&x1_ptr,  d_x1);
    float* x2h_ptr; cudaGetSymbolAddress((void**)&x2h_ptr, d_x2h);

    k_zero<<<ZN / 256, 256>>>();                               // 1
    k_count_mh<<<(EE + 255) / 256, 256>>>(dst, hostidx);       // 2
    k_scan<<<1, 1024>>>();                                     // 3
    // stage-0 attention — slot 4 → profiled (f32x2 phase A version)
    k_attn<IN_F, H1><<<BB, 256>>>(x, hostidx, a0W, a0b, f0W, f0b, g0W, g0b);    // 4
    k_gemm1<<<NN / G1R, 256>>>(x, W1);                         // 5
    k_fill_me<<<(EE + 255) / 256, 256>>>(src, dst);            // 6
    k_mklist<<<NN / 256, 256>>>();                             // 7

    // layer 1
    k_agg1<<<NN, 256>>>(b1);                                   // 8
    k_attn<H1, H1><<<BB, 256>>>(x1_ptr, hostidx, a1W, a1b, f1W, f1b, g1W, g1b); // 9

    // layer 2
    k_gemm2<<<(NN + G2R - 1) / G2R, 256>>>(W2);                // 10
    k_agg2<<<BB * NHOST, 64>>>(hostidx, b2);                   // 11
    k_attn<H2, H2><<<BB, 256>>>(x2h_ptr, (const int*)nullptr, a2W, a2b, f2W, f2b, g2W, g2b); // 12

    // head
    k_head<<<BB, 64>>>(o1W, o1b, o2W, o2b, out);               // 13
}

// round 11
// speedup vs baseline: 1.9731x; 1.0040x over previous
#include <cuda_runtime.h>
#include <math.h>

#define NN 51200      // nodes
#define EE 409600     // edges (without self loops)
#define BB 256        // batch
#define NHOST 13
#define IN_F 64
#define H1 256
#define H2 64
#define ZN 65536      // max(NN, BB*H1) — elements to zero

typedef unsigned long long u64;

// ---------------- scratch (static device globals; no runtime alloc) -------
__device__ int   d_cnt[NN];
__device__ int   d_off[NN + 1];
__device__ int   d_cur[NN];
__device__ int   d_csr[EE];
__device__ int   d_flag[NN];
__device__ int   d_ishost[NN];
__device__ int   d_list[NN];
__device__ int   d_nf;
__device__ float d_dinv[NN];
__device__ float d_xw[(size_t)NN * H1];    // dinv * (x @ W1)
__device__ float d_x1[(size_t)NN * H1];    // relu(agg1 + b1) on frontier rows
__device__ float d_xw2[(size_t)NN * H2];   // dinv * (x1 @ W2), frontier rows only
__device__ float d_x2h[(size_t)BB * NHOST * H2];
__device__ float d_g[(size_t)BB * H1];     // global state

// ---------------- zero ------------------------------------------------------
__global__ void k_zero() {
    int i = blockIdx.x * blockDim.x + threadIdx.x;
    if (i < NN) { d_cnt[i] = 0; d_flag[i] = 0; d_ishost[i] = 0; }
    if (i < BB * H1) d_g[i] = 0.f;
    if (i == 0) d_nf = 0;
}

__global__ void k_count_mh(const int* __restrict__ dst, const int* __restrict__ hidx) {
    int e = blockIdx.x * blockDim.x + threadIdx.x;
    if (e < EE) atomicAdd(&d_cnt[dst[e]], 1);
    if (e < BB * NHOST) {
        int n = hidx[e];
        d_ishost[n] = 1;
        d_flag[n] = 1;
    }
}

// 1 block, 1024 threads, 50 items each
__global__ void k_scan() {
    __shared__ int part[1024];
    int t = threadIdx.x;
    int base = t * 50;
    int s = 0;
    for (int i = 0; i < 50; i++) s += d_cnt[base + i];
    part[t] = s;
    __syncthreads();
    for (int d = 1; d < 1024; d <<= 1) {
        int v = part[t];
        int add = (t >= d) ? part[t - d] : 0;
        __syncthreads();
        part[t] = v + add;
        __syncthreads();
    }
    int run = part[t] - s;
    for (int i = 0; i < 50; i++) {
        int c = d_cnt[base + i];
        d_off[base + i] = run;
        d_cur[base + i] = run;
        d_dinv[base + i] = rsqrtf((float)(c + 1));
        run += c;
    }
    if (t == 1023) d_off[NN] = run;
}

__global__ void k_fill_me(const int* __restrict__ src, const int* __restrict__ dst) {
    int e = blockIdx.x * blockDim.x + threadIdx.x;
    if (e < EE) {
        int d = dst[e];
        int s = src[e];
        int p = atomicAdd(&d_cur[d], 1);
        d_csr[p] = s;
        if (d_ishost[d]) d_flag[s] = 1;
    }
}

__global__ void k_mklist() {
    int i = blockIdx.x * blockDim.x + threadIdx.x;
    if (i < NN && d_flag[i]) {
        int p = atomicAdd(&d_nf, 1);
        d_list[p] = i;
    }
}

// ---------------- GEMM1: xw = dinv * (x @ W1)  [51200,64]x[64,256] ---------
#define G1R 32
__global__ void k_gemm1(const float* __restrict__ x, const float* __restrict__ W1) {
    __shared__ float xs[IN_F][G1R + 2];
    int r0 = blockIdx.x * G1R;
    int t = threadIdx.x; // 256
    int rg = t >> 6;
    int cg = t & 63;
    for (int i = t; i < G1R * IN_F; i += 256) {
        int r = i >> 6, k = i & 63;
        xs[k][r] = x[(size_t)(r0 + r) * IN_F + k];
    }
    __syncthreads();
    u64 acc[4][4];
#pragma unroll
    for (int p = 0; p < 4; p++)
#pragma unroll
        for (int c = 0; c < 4; c++) acc[p][c] = 0ull;
    for (int k = 0; k < IN_F; k++) {
        float4 w4 = *reinterpret_cast<const float4*>(&W1[k * H1 + cg * 4]);
        u64 wd[4];
        asm("mov.b64 %0, {%1, %1};" : "=l"(wd[0]) : "f"(w4.x));
        asm("mov.b64 %0, {%1, %1};" : "=l"(wd[1]) : "f"(w4.y));
        asm("mov.b64 %0, {%1, %1};" : "=l"(wd[2]) : "f"(w4.z));
        asm("mov.b64 %0, {%1, %1};" : "=l"(wd[3]) : "f"(w4.w));
        u64 xp[4];
#pragma unroll
        for (int p = 0; p < 4; p++)
            xp[p] = *reinterpret_cast<const u64*>(&xs[k][rg * 8 + 2 * p]);
#pragma unroll
        for (int p = 0; p < 4; p++)
#pragma unroll
            for (int c = 0; c < 4; c++)
                asm("fma.rn.f32x2 %0, %1, %2, %0;" : "+l"(acc[p][c]) : "l"(xp[p]), "l"(wd[c]));
    }
#pragma unroll
    for (int p = 0; p < 4; p++) {
        float lo[4], hi[4];
#pragma unroll
        for (int c = 0; c < 4; c++)
            asm("mov.b64 {%0, %1}, %2;" : "=f"(lo[c]), "=f"(hi[c]) : "l"(acc[p][c]));
        int ra = r0 + rg * 8 + 2 * p;
        float da = d_dinv[ra], db = d_dinv[ra + 1];
        float4 oa = make_float4(da * lo[0], da * lo[1], da * lo[2], da * lo[3]);
        float4 ob = make_float4(db * hi[0], db * hi[1], db * hi[2], db * hi[3]);
        *reinterpret_cast<float4*>(&d_xw[(size_t)ra * H1 + cg * 4])       = oa;
        *reinterpret_cast<float4*>(&d_xw[(size_t)(ra + 1) * H1 + cg * 4]) = ob;
    }
}

// ---------------- layer-1 max aggregation (frontier list; no barriers) -----
// Neighbor indices are uniform per block → __ldg broadcasts. 8-wide unroll
// puts 8 idx + 8 row loads in flight (MLP 16), zero __syncthreads.
__global__ void k_agg1(const float* __restrict__ b1) {
    int bi = blockIdx.x;
    if (bi >= d_nf) return;
    int i = d_list[bi];
    int t = threadIdx.x; // 256
    float m = d_xw[(size_t)i * H1 + t];
    int e0 = d_off[i], e1 = d_off[i + 1];
    int e = e0;
    for (; e + 8 <= e1; e += 8) {
        int s0 = __ldg(&d_csr[e]);
        int s1 = __ldg(&d_csr[e + 1]);
        int s2 = __ldg(&d_csr[e + 2]);
        int s3 = __ldg(&d_csr[e + 3]);
        int s4 = __ldg(&d_csr[e + 4]);
        int s5 = __ldg(&d_csr[e + 5]);
        int s6 = __ldg(&d_csr[e + 6]);
        int s7 = __ldg(&d_csr[e + 7]);
        float v0 = __ldg(&d_xw[(size_t)s0 * H1 + t]);
        float v1 = __ldg(&d_xw[(size_t)s1 * H1 + t]);
        float v2 = __ldg(&d_xw[(size_t)s2 * H1 + t]);
        float v3 = __ldg(&d_xw[(size_t)s3 * H1 + t]);
        float v4 = __ldg(&d_xw[(size_t)s4 * H1 + t]);
        float v5 = __ldg(&d_xw[(size_t)s5 * H1 + t]);
        float v6 = __ldg(&d_xw[(size_t)s6 * H1 + t]);
        float v7 = __ldg(&d_xw[(size_t)s7 * H1 + t]);
        float m0 = fmaxf(fmaxf(v0, v1), fmaxf(v2, v3));
        float m1 = fmaxf(fmaxf(v4, v5), fmaxf(v6, v7));
        m = fmaxf(m, fmaxf(m0, m1));
    }
    for (; e < e1; e++)
        m = fmaxf(m, __ldg(&d_xw[(size_t)__ldg(&d_csr[e]) * H1 + t]));
    d_x1[(size_t)i * H1 + t] = fmaxf(d_dinv[i] * m + b1[t], 0.f);
}

// ---------------- GEMM2 on frontier rows: xw2 = dinv * (x1 @ W2) -----------
#define G2R 128
__global__ void k_gemm2(const float* __restrict__ W2) {
    int r0 = blockIdx.x * G2R;
    int nf = d_nf;
    if (r0 >= nf) return;
    __shared__ float xs[64][G2R + 2];
    __shared__ int rows[G2R];
    int t = threadIdx.x;      // 256
    int rg = t >> 4;
    int cg = t & 15;
    if (t < G2R) rows[t] = d_list[min(r0 + t, nf - 1)];
    __syncthreads();
    u64 acc[4][4];
#pragma unroll
    for (int p = 0; p < 4; p++)
#pragma unroll
        for (int c = 0; c < 4; c++) acc[p][c] = 0ull;
    for (int kc = 0; kc < H1; kc += 64) {
        __syncthreads();
        for (int i = t; i < G2R * 64; i += 256) {
            int r = i >> 6, k = i & 63;
            xs[k][r] = d_x1[(size_t)rows[r] * H1 + kc + k];
        }
        __syncthreads();
        for (int k = 0; k < 64; k++) {
            float4 w4 = *reinterpret_cast<const float4*>(&W2[(kc + k) * H2 + cg * 4]);
            u64 wd[4];
            asm("mov.b64 %0, {%1, %1};" : "=l"(wd[0]) : "f"(w4.x));
            asm("mov.b64 %0, {%1, %1};" : "=l"(wd[1]) : "f"(w4.y));
            asm("mov.b64 %0, {%1, %1};" : "=l"(wd[2]) : "f"(w4.z));
            asm("mov.b64 %0, {%1, %1};" : "=l"(wd[3]) : "f"(w4.w));
            u64 xp[4];
#pragma unroll
            for (int p = 0; p < 4; p++)
                xp[p] = *reinterpret_cast<const u64*>(&xs[k][rg * 8 + 2 * p]);
#pragma unroll
            for (int p = 0; p < 4; p++)
#pragma unroll
                for (int c = 0; c < 4; c++)
                    asm("fma.rn.f32x2 %0, %1, %2, %0;" : "+l"(acc[p][c]) : "l"(xp[p]), "l"(wd[c]));
        }
    }
#pragma unroll
    for (int p = 0; p < 4; p++) {
        float lo[4], hi[4];
#pragma unroll
        for (int c = 0; c < 4; c++)
            asm("mov.b64 {%0, %1}, %2;" : "=f"(lo[c]), "=f"(hi[c]) : "l"(acc[p][c]));
        int rla = rg * 8 + 2 * p;
        int ga = rows[rla], gb2 = rows[rla + 1];
        float da = d_dinv[ga], db = d_dinv[gb2];
        float4 oa = make_float4(da * lo[0], da * lo[1], da * lo[2], da * lo[3]);
        float4 ob = make_float4(db * hi[0], db * hi[1], db * hi[2], db * hi[3]);
        *reinterpret_cast<float4*>(&d_xw2[(size_t)ga * H2 + cg * 4])  = oa;
        *reinterpret_cast<float4*>(&d_xw2[(size_t)gb2 * H2 + cg * 4]) = ob;
    }
}

// ---------------- layer-2 max aggregation (HOST nodes; no barriers) --------
__global__ void k_agg2(const int* __restrict__ hidx, const float* __restrict__ b2) {
    int hi = blockIdx.x;
    int t = threadIdx.x;       // 64
    int node = __ldg(&hidx[hi]);
    float m = d_xw2[(size_t)node * H2 + t];
    int e0 = d_off[node], e1 = d_off[node + 1];
    int e = e0;
    for (; e + 8 <= e1; e += 8) {
        int s0 = __ldg(&d_csr[e]);
        int s1 = __ldg(&d_csr[e + 1]);
        int s2 = __ldg(&d_csr[e + 2]);
        int s3 = __ldg(&d_csr[e + 3]);
        int s4 = __ldg(&d_csr[e + 4]);
        int s5 = __ldg(&d_csr[e + 5]);
        int s6 = __ldg(&d_csr[e + 6]);
        int s7 = __ldg(&d_csr[e + 7]);
        float v0 = __ldg(&d_xw2[(size_t)s0 * H2 + t]);
        float v1 = __ldg(&d_xw2[(size_t)s1 * H2 + t]);
        float v2 = __ldg(&d_xw2[(size_t)s2 * H2 + t]);
        float v3 = __ldg(&d_xw2[(size_t)s3 * H2 + t]);
        float v4 = __ldg(&d_xw2[(size_t)s4 * H2 + t]);
        float v5 = __ldg(&d_xw2[(size_t)s5 * H2 + t]);
        float v6 = __ldg(&d_xw2[(size_t)s6 * H2 + t]);
        float v7 = __ldg(&d_xw2[(size_t)s7 * H2 + t]);
        float m0 = fmaxf(fmaxf(v0, v1), fmaxf(v2, v3));
        float m1 = fmaxf(fmaxf(v4, v5), fmaxf(v6, v7));
        m = fmaxf(m, fmaxf(m0, m1));
    }
    for (; e < e1; e++)
        m = fmaxf(m, __ldg(&d_xw2[(size_t)__ldg(&d_csr[e]) * H2 + t]));
    d_x2h[(size_t)hi * H2 + t] = fmaxf(d_dinv[node] * m + b2[t], 0.f);
}

// ---------------- self attention — r10 skeleton, phase A unrolled ×4 -------
template <int F, int H>
__global__ void k_attn(const float* __restrict__ v, const int* __restrict__ hidx,
                       const float* __restrict__ aW, const float* __restrict__ ab,
                       const float* __restrict__ fW, const float* __restrict__ fb,
                       const float* __restrict__ gW, const float* __restrict__ gb) {
    int b = blockIdx.x;
    int t = threadIdx.x;           // 256
    int lane = t & 31, w = t >> 5; // 8 warps

    __shared__ float vsT[F][14];
    __shared__ float ls[NHOST * H];
    __shared__ float fs[NHOST * H];
    __shared__ float mx[NHOST], rinv[NHOST];
    __shared__ float outs[H];
    __shared__ float gs[H1];

    for (int i = t; i < NHOST * F; i += 256) {
        int h = i / F, f = i % F;
        int row = hidx ? hidx[b * NHOST + h] : (b * NHOST + h);
        vsT[f][h] = v[(size_t)row * F + f];
    }
    for (int f = t; f < F; f += 256) vsT[f][13] = 0.f;
    gs[t] = d_g[(size_t)b * H1 + t];
    __syncthreads();

    // Phase A: aL/fV for 13 hosts, 7 f32x2 pairs; f unrolled ×4 (MLP 8)
    if (t < H) {
        u64 aLp[7], fVp[7];
#pragma unroll
        for (int p = 0; p < 7; p++) { aLp[p] = 0ull; fVp[p] = 0ull; }
        for (int f = 0; f < F; f += 4) {
            float wa[4], wf[4];
#pragma unroll
            for (int j = 0; j < 4; j++) {
                wa[j] = __ldg(&aW[(f + j) * H + t]);
                wf[j] = __ldg(&fW[(f + j) * H + t]);
            }
#pragma unroll
            for (int j = 0; j < 4; j++) {
                u64 wa2, wf2;
                asm("mov.b64 %0, {%1, %1};" : "=l"(wa2) : "f"(wa[j]));
                asm("mov.b64 %0, {%1, %1};" : "=l"(wf2) : "f"(wf[j]));
#pragma unroll
                for (int p = 0; p < 7; p++) {
                    u64 xv = *reinterpret_cast<const u64*>(&vsT[f + j][2 * p]);
                    asm("fma.rn.f32x2 %0, %1, %2, %0;" : "+l"(aLp[p]) : "l"(xv), "l"(wa2));
                    asm("fma.rn.f32x2 %0, %1, %2, %0;" : "+l"(fVp[p]) : "l"(xv), "l"(wf2));
                }
            }
        }
        float abv = __ldg(&ab[t]), fbv = __ldg(&fb[t]);
#pragma unroll
        for (int p = 0; p < 7; p++) {
            float alo, ahi, flo, fhi;
            asm("mov.b64 {%0, %1}, %2;" : "=f"(alo), "=f"(ahi) : "l"(aLp[p]));
            asm("mov.b64 {%0, %1}, %2;" : "=f"(flo), "=f"(fhi) : "l"(fVp[p]));
            ls[(2 * p) * H + t] = alo + abv;
            fs[(2 * p) * H + t] = flo + fbv;
            if (2 * p + 1 < NHOST) {
                ls[(2 * p + 1) * H + t] = ahi + abv;
                fs[(2 * p + 1) * H + t] = fhi + fbv;
            }
        }
    }
    __syncthreads();

    // Phase B1: per-host max via warp reductions
    for (int h = w; h < NHOST; h += 8) {
        float m = -1e30f;
        for (int j = lane; j < H; j += 32) m = fmaxf(m, ls[h * H + j]);
#pragma unroll
        for (int d = 16; d > 0; d >>= 1) m = fmaxf(m, __shfl_xor_sync(0xffffffffu, m, d));
        if (lane == 0) mx[h] = m;
    }
    __syncthreads();
    // Phase B2: exp
    for (int i = t; i < NHOST * H; i += 256) ls[i] = expf(ls[i] - mx[i / H]);
    __syncthreads();
    // Phase B3: per-host sum via warp reductions
    for (int h = w; h < NHOST; h += 8) {
        float s = 0.f;
        for (int j = lane; j < H; j += 32) s += ls[h * H + j];
#pragma unroll
        for (int d = 16; d > 0; d >>= 1) s += __shfl_xor_sync(0xffffffffu, s, d);
        if (lane == 0) rinv[h] = 1.0f / s;
    }
    __syncthreads();

    // Phase C: weighted sum over hosts
    if (t < H) {
        float o = 0.f;
#pragma unroll
        for (int h = 0; h < NHOST; h++)
            o += ls[h * H + t] * rinv[h] * fs[h * H + t];
        outs[t] = o;
    }
    __syncthreads();

    // Phase D: g_new = concat(out,g) @ gW + gb ; g += g_new  (4 indep accs)
    float a0 = __ldg(&gb[t]), a1 = 0.f, a2 = 0.f, a3 = 0.f;
    for (int k = 0; k < H; k += 4) {
        a0 += outs[k]     * __ldg(&gW[(k)     * H1 + t]);
        a1 += outs[k + 1] * __ldg(&gW[(k + 1) * H1 + t]);
        a2 += outs[k + 2] * __ldg(&gW[(k + 2) * H1 + t]);
        a3 += outs[k + 3] * __ldg(&gW[(k + 3) * H1 + t]);
    }
    for (int k = 0; k < H1; k += 4) {
        a0 += gs[k]     * __ldg(&gW[(H + k)     * H1 + t]);
        a1 += gs[k + 1] * __ldg(&gW[(H + k + 1) * H1 + t]);
        a2 += gs[k + 2] * __ldg(&gW[(H + k + 2) * H1 + t]);
        a3 += gs[k + 3] * __ldg(&gW[(H + k + 3) * H1 + t]);
    }
    d_g[(size_t)b * H1 + t] = gs[t] + (a0 + a1) + (a2 + a3);
}

// ---------------- final head: relu(g@o1W+o1b)@o2W + o2b -------------------
__global__ void k_head(const float* __restrict__ o1W, const float* __restrict__ o1b,
                       const float* __restrict__ o2W, const float* __restrict__ o2b,
                       float* __restrict__ out) {
    int b = blockIdx.x;
    int t = threadIdx.x; // 64
    __shared__ float gs[H1];
    for (int i = t; i < H1; i += 64) gs[i] = d_g[(size_t)b * H1 + i];
    __syncthreads();
    float a0 = o1b[t], a1 = 0.f, a2 = 0.f, a3 = 0.f;
    for (int k = 0; k < H1; k += 4) {
        a0 += gs[k]     * __ldg(&o1W[(k)     * H2 + t]);
        a1 += gs[k + 1] * __ldg(&o1W[(k + 1) * H2 + t]);
        a2 += gs[k + 2] * __ldg(&o1W[(k + 2) * H2 + t]);
        a3 += gs[k + 3] * __ldg(&o1W[(k + 3) * H2 + t]);
    }
    float acc = (a0 + a1) + (a2 + a3);
    float v = fmaxf(acc, 0.f) * __ldg(&o2W[t]);
    __shared__ float rs[64];
    rs[t] = v;
    __syncthreads();
    if (t < 32) {
        float s = rs[t] + rs[t + 32];
#pragma unroll
        for (int d = 16; d > 0; d >>= 1) s += __shfl_down_sync(0xffffffffu, s, d);
        if (t == 0) out[b] = s + o2b[0];
    }
}

// ---------------- launch ---------------------------------------------------
extern "C" void kernel_launch(void* const* d_in, const int* in_sizes, int n_in,
                              void* d_out, int out_size) {
    const float* x       = (const float*)d_in[0];
    const int*   ei      = (const int*)d_in[1];
    const int*   hostidx = (const int*)d_in[2];
    const float* W1 = (const float*)d_in[3];
    const float* b1 = (const float*)d_in[4];
    const float* W2 = (const float*)d_in[5];
    const float* b2 = (const float*)d_in[6];
    const float* a0W = (const float*)d_in[7];  const float* a0b = (const float*)d_in[8];
    const float* f0W = (const float*)d_in[9];  const float* f0b = (const float*)d_in[10];
    const float* g0W = (const float*)d_in[11]; const float* g0b = (const float*)d_in[12];
    const float* a1W = (const float*)d_in[13]; const float* a1b = (const float*)d_in[14];
    const float* f1W = (const float*)d_in[15]; const float* f1b = (const float*)d_in[16];
    const float* g1W = (const float*)d_in[17]; const float* g1b = (const float*)d_in[18];
    const float* a2W = (const float*)d_in[19]; const float* a2b = (const float*)d_in[20];
    const float* f2W = (const float*)d_in[21]; const float* f2b = (const float*)d_in[22];
    const float* g2W = (const float*)d_in[23]; const float* g2b = (const float*)d_in[24];
    const float* o1W = (const float*)d_in[25]; const float* o1b = (const float*)d_in[26];
    const float* o2W = (const float*)d_in[27]; const float* o2b = (const float*)d_in[28];
    float* out = (float*)d_out;

    const int* src = ei;
    const int* dst = ei + EE;

    float* x1_ptr;  cudaGetSymbolAddress((void**)&x1_ptr,  d_x1);
    float* x2h_ptr; cudaGetSymbolAddress((void**)&x2h_ptr, d_x2h);

    k_zero<<<ZN / 256, 256>>>();                               // 1
    k_count_mh<<<(EE + 255) / 256, 256>>>(dst, hostidx);       // 2
    k_scan<<<1, 1024>>>();                                     // 3
    // stage-0 attention — slot 4 → profiled (phase-A unroll verification)
    k_attn<IN_F, H1><<<BB, 256>>>(x, hostidx, a0W, a0b, f0W, f0b, g0W, g0b);    // 4
    k_gemm1<<<NN / G1R, 256>>>(x, W1);                         // 5
    k_fill_me<<<(EE + 255) / 256, 256>>>(src, dst);            // 6
    k_mklist<<<NN / 256, 256>>>();                             // 7

    // layer 1
    k_agg1<<<NN, 256>>>(b1);                                   // 8
    k_attn<H1, H1><<<BB, 256>>>(x1_ptr, hostidx, a1W, a1b, f1W, f1b, g1W, g1b); // 9

    // layer 2
    k_gemm2<<<(NN + G2R - 1) / G2R, 256>>>(W2);                // 10
    k_agg2<<<BB * NHOST, 64>>>(hostidx, b2);                   // 11
    k_attn<H2, H2><<<BB, 256>>>(x2h_ptr, (const int*)nullptr, a2W, a2b, f2W, f2b, g2W, g2b); // 12

    // head
    k_head<<<BB, 64>>>(o1W, o1b, o2W, o2b, out);               // 13
}

// round 12
// speedup vs baseline: 2.5898x; 1.3125x over previous
#include <cuda_runtime.h>
#include <math.h>

#define NN 51200      // nodes
#define EE 409600     // edges (without self loops)
#define BB 256        // batch
#define NHOST 13
#define IN_F 64
#define H1 256
#define H2 64
#define ZN 65536      // max(NN, BB*H1) — elements to zero
#define NB 200        // NN / 256 scan blocks

typedef unsigned long long u64;

// ---------------- scratch (static device globals; no runtime alloc) -------
__device__ int   d_cnt[NN];
__device__ int   d_off[NN + 1];
__device__ int   d_cur[NN];
__device__ int   d_csr[EE];
__device__ int   d_flag[NN];
__device__ int   d_ishost[NN];
__device__ int   d_list[NN];
__device__ int   d_nf;
__device__ int   d_bsum[NB];
__device__ int   d_bbase[NB];
__device__ float d_dinv[NN];
__device__ float d_xw[(size_t)NN * H1];    // dinv * (x @ W1)
__device__ float d_x1[(size_t)NN * H1];    // relu(agg1 + b1) on frontier rows
__device__ float d_xw2[(size_t)NN * H2];   // dinv * (x1 @ W2), frontier rows only
__device__ float d_x2h[(size_t)BB * NHOST * H2];
__device__ float d_g[(size_t)BB * H1];     // global state

// ---------------- zero ------------------------------------------------------
__global__ void k_zero() {
    int i = blockIdx.x * blockDim.x + threadIdx.x;
    if (i < NN) { d_cnt[i] = 0; d_flag[i] = 0; d_ishost[i] = 0; }
    if (i < BB * H1) d_g[i] = 0.f;
    if (i == 0) d_nf = 0;
}

__global__ void k_count_mh(const int* __restrict__ dst, const int* __restrict__ hidx) {
    int e = blockIdx.x * blockDim.x + threadIdx.x;
    if (e < EE) atomicAdd(&d_cnt[dst[e]], 1);
    if (e < BB * NHOST) {
        int n = hidx[e];
        d_ishost[n] = 1;
        d_flag[n] = 1;
    }
}

// ---------------- parallel 3-phase scan -------------------------------------
// phase 1: per-block sums of 256 counts (grid NB, 256 thr, coalesced)
__global__ void k_scan1() {
    __shared__ int sh[256];
    int t = threadIdx.x;
    sh[t] = d_cnt[blockIdx.x * 256 + t];
    __syncthreads();
#pragma unroll
    for (int d = 128; d > 0; d >>= 1) {
        if (t < d) sh[t] += sh[t + d];
        __syncthreads();
    }
    if (t == 0) d_bsum[blockIdx.x] = sh[0];
}

// phase 2: exclusive scan of NB block sums (1 block, 256 thr)
__global__ void k_scan2() {
    __shared__ int sh[256];
    int t = threadIdx.x;
    int v = (t < NB) ? d_bsum[t] : 0;
    sh[t] = v;
    __syncthreads();
#pragma unroll
    for (int d = 1; d < 256; d <<= 1) {
        int x = sh[t];
        int add = (t >= d) ? sh[t - d] : 0;
        __syncthreads();
        sh[t] = x + add;
        __syncthreads();
    }
    if (t < NB) d_bbase[t] = sh[t] - v;  // exclusive
}

// phase 3: intra-block exclusive scan + emit off/cur/dinv (grid NB, 256 thr)
__global__ void k_scan3() {
    __shared__ int sh[256];
    int t = threadIdx.x;
    int i = blockIdx.x * 256 + t;
    int c = d_cnt[i];
    sh[t] = c;
    __syncthreads();
#pragma unroll
    for (int d = 1; d < 256; d <<= 1) {
        int x = sh[t];
        int add = (t >= d) ? sh[t - d] : 0;
        __syncthreads();
        sh[t] = x + add;
        __syncthreads();
    }
    int off = d_bbase[blockIdx.x] + sh[t] - c;  // exclusive prefix
    d_off[i] = off;
    d_cur[i] = off;
    d_dinv[i] = rsqrtf((float)(c + 1));  // +1 self loop
    if (i == 0) d_off[NN] = EE;          // total is a compile-time constant
}

__global__ void k_fill_me(const int* __restrict__ src, const int* __restrict__ dst) {
    int e = blockIdx.x * blockDim.x + threadIdx.x;
    if (e < EE) {
        int d = dst[e];
        int s = src[e];
        int p = atomicAdd(&d_cur[d], 1);
        d_csr[p] = s;
        if (d_ishost[d]) d_flag[s] = 1;
    }
}

__global__ void k_mklist() {
    int i = blockIdx.x * blockDim.x + threadIdx.x;
    if (i < NN && d_flag[i]) {
        int p = atomicAdd(&d_nf, 1);
        d_list[p] = i;
    }
}

// ---------------- GEMM1: xw = dinv * (x @ W1)  [51200,64]x[64,256] ---------
#define G1R 32
__global__ void k_gemm1(const float* __restrict__ x, const float* __restrict__ W1) {
    __shared__ float xs[IN_F][G1R + 2];
    int r0 = blockIdx.x * G1R;
    int t = threadIdx.x; // 256
    int rg = t >> 6;
    int cg = t & 63;
    for (int i = t; i < G1R * IN_F; i += 256) {
        int r = i >> 6, k = i & 63;
        xs[k][r] = x[(size_t)(r0 + r) * IN_F + k];
    }
    __syncthreads();
    u64 acc[4][4];
#pragma unroll
    for (int p = 0; p < 4; p++)
#pragma unroll
        for (int c = 0; c < 4; c++) acc[p][c] = 0ull;
    for (int k = 0; k < IN_F; k++) {
        float4 w4 = *reinterpret_cast<const float4*>(&W1[k * H1 + cg * 4]);
        u64 wd[4];
        asm("mov.b64 %0, {%1, %1};" : "=l"(wd[0]) : "f"(w4.x));
        asm("mov.b64 %0, {%1, %1};" : "=l"(wd[1]) : "f"(w4.y));
        asm("mov.b64 %0, {%1, %1};" : "=l"(wd[2]) : "f"(w4.z));
        asm("mov.b64 %0, {%1, %1};" : "=l"(wd[3]) : "f"(w4.w));
        u64 xp[4];
#pragma unroll
        for (int p = 0; p < 4; p++)
            xp[p] = *reinterpret_cast<const u64*>(&xs[k][rg * 8 + 2 * p]);
#pragma unroll
        for (int p = 0; p < 4; p++)
#pragma unroll
            for (int c = 0; c < 4; c++)
                asm("fma.rn.f32x2 %0, %1, %2, %0;" : "+l"(acc[p][c]) : "l"(xp[p]), "l"(wd[c]));
    }
#pragma unroll
    for (int p = 0; p < 4; p++) {
        float lo[4], hi[4];
#pragma unroll
        for (int c = 0; c < 4; c++)
            asm("mov.b64 {%0, %1}, %2;" : "=f"(lo[c]), "=f"(hi[c]) : "l"(acc[p][c]));
        int ra = r0 + rg * 8 + 2 * p;
        float da = d_dinv[ra], db = d_dinv[ra + 1];
        float4 oa = make_float4(da * lo[0], da * lo[1], da * lo[2], da * lo[3]);
        float4 ob = make_float4(db * hi[0], db * hi[1], db * hi[2], db * hi[3]);
        *reinterpret_cast<float4*>(&d_xw[(size_t)ra * H1 + cg * 4])       = oa;
        *reinterpret_cast<float4*>(&d_xw[(size_t)(ra + 1) * H1 + cg * 4]) = ob;
    }
}

// ---------------- layer-1 max aggregation (frontier list; no barriers) -----
__global__ void k_agg1(const float* __restrict__ b1) {
    int bi = blockIdx.x;
    if (bi >= d_nf) return;
    int i = d_list[bi];
    int t = threadIdx.x; // 256
    float m = d_xw[(size_t)i * H1 + t];
    int e0 = d_off[i], e1 = d_off[i + 1];
    int e = e0;
    for (; e + 8 <= e1; e += 8) {
        int s0 = __ldg(&d_csr[e]);
        int s1 = __ldg(&d_csr[e + 1]);
        int s2 = __ldg(&d_csr[e + 2]);
        int s3 = __ldg(&d_csr[e + 3]);
        int s4 = __ldg(&d_csr[e + 4]);
        int s5 = __ldg(&d_csr[e + 5]);
        int s6 = __ldg(&d_csr[e + 6]);
        int s7 = __ldg(&d_csr[e + 7]);
        float v0 = __ldg(&d_xw[(size_t)s0 * H1 + t]);
        float v1 = __ldg(&d_xw[(size_t)s1 * H1 + t]);
        float v2 = __ldg(&d_xw[(size_t)s2 * H1 + t]);
        float v3 = __ldg(&d_xw[(size_t)s3 * H1 + t]);
        float v4 = __ldg(&d_xw[(size_t)s4 * H1 + t]);
        float v5 = __ldg(&d_xw[(size_t)s5 * H1 + t]);
        float v6 = __ldg(&d_xw[(size_t)s6 * H1 + t]);
        float v7 = __ldg(&d_xw[(size_t)s7 * H1 + t]);
        float m0 = fmaxf(fmaxf(v0, v1), fmaxf(v2, v3));
        float m1 = fmaxf(fmaxf(v4, v5), fmaxf(v6, v7));
        m = fmaxf(m, fmaxf(m0, m1));
    }
    for (; e < e1; e++)
        m = fmaxf(m, __ldg(&d_xw[(size_t)__ldg(&d_csr[e]) * H1 + t]));
    d_x1[(size_t)i * H1 + t] = fmaxf(d_dinv[i] * m + b1[t], 0.f);
}

// ---------------- GEMM2 on frontier rows: xw2 = dinv * (x1 @ W2) -----------
#define G2R 128
__global__ void k_gemm2(const float* __restrict__ W2) {
    int r0 = blockIdx.x * G2R;
    int nf = d_nf;
    if (r0 >= nf) return;
    __shared__ float xs[64][G2R + 2];
    __shared__ int rows[G2R];
    int t = threadIdx.x;      // 256
    int rg = t >> 4;
    int cg = t & 15;
    if (t < G2R) rows[t] = d_list[min(r0 + t, nf - 1)];
    __syncthreads();
    u64 acc[4][4];
#pragma unroll
    for (int p = 0; p < 4; p++)
#pragma unroll
        for (int c = 0; c < 4; c++) acc[p][c] = 0ull;
    for (int kc = 0; kc < H1; kc += 64) {
        __syncthreads();
        for (int i = t; i < G2R * 64; i += 256) {
            int r = i >> 6, k = i & 63;
            xs[k][r] = d_x1[(size_t)rows[r] * H1 + kc + k];
        }
        __syncthreads();
        for (int k = 0; k < 64; k++) {
            float4 w4 = *reinterpret_cast<const float4*>(&W2[(kc + k) * H2 + cg * 4]);
            u64 wd[4];
            asm("mov.b64 %0, {%1, %1};" : "=l"(wd[0]) : "f"(w4.x));
            asm("mov.b64 %0, {%1, %1};" : "=l"(wd[1]) : "f"(w4.y));
            asm("mov.b64 %0, {%1, %1};" : "=l"(wd[2]) : "f"(w4.z));
            asm("mov.b64 %0, {%1, %1};" : "=l"(wd[3]) : "f"(w4.w));
            u64 xp[4];
#pragma unroll
            for (int p = 0; p < 4; p++)
                xp[p] = *reinterpret_cast<const u64*>(&xs[k][rg * 8 + 2 * p]);
#pragma unroll
            for (int p = 0; p < 4; p++)
#pragma unroll
                for (int c = 0; c < 4; c++)
                    asm("fma.rn.f32x2 %0, %1, %2, %0;" : "+l"(acc[p][c]) : "l"(xp[p]), "l"(wd[c]));
        }
    }
#pragma unroll
    for (int p = 0; p < 4; p++) {
        float lo[4], hi[4];
#pragma unroll
        for (int c = 0; c < 4; c++)
            asm("mov.b64 {%0, %1}, %2;" : "=f"(lo[c]), "=f"(hi[c]) : "l"(acc[p][c]));
        int rla = rg * 8 + 2 * p;
        int ga = rows[rla], gb2 = rows[rla + 1];
        float da = d_dinv[ga], db = d_dinv[gb2];
        float4 oa = make_float4(da * lo[0], da * lo[1], da * lo[2], da * lo[3]);
        float4 ob = make_float4(db * hi[0], db * hi[1], db * hi[2], db * hi[3]);
        *reinterpret_cast<float4*>(&d_xw2[(size_t)ga * H2 + cg * 4])  = oa;
        *reinterpret_cast<float4*>(&d_xw2[(size_t)gb2 * H2 + cg * 4]) = ob;
    }
}

// ---------------- layer-2 max aggregation (HOST nodes; no barriers) --------
__global__ void k_agg2(const int* __restrict__ hidx, const float* __restrict__ b2) {
    int hi = blockIdx.x;
    int t = threadIdx.x;       // 64
    int node = __ldg(&hidx[hi]);
    float m = d_xw2[(size_t)node * H2 + t];
    int e0 = d_off[node], e1 = d_off[node + 1];
    int e = e0;
    for (; e + 8 <= e1; e += 8) {
        int s0 = __ldg(&d_csr[e]);
        int s1 = __ldg(&d_csr[e + 1]);
        int s2 = __ldg(&d_csr[e + 2]);
        int s3 = __ldg(&d_csr[e + 3]);
        int s4 = __ldg(&d_csr[e + 4]);
        int s5 = __ldg(&d_csr[e + 5]);
        int s6 = __ldg(&d_csr[e + 6]);
        int s7 = __ldg(&d_csr[e + 7]);
        float v0 = __ldg(&d_xw2[(size_t)s0 * H2 + t]);
        float v1 = __ldg(&d_xw2[(size_t)s1 * H2 + t]);
        float v2 = __ldg(&d_xw2[(size_t)s2 * H2 + t]);
        float v3 = __ldg(&d_xw2[(size_t)s3 * H2 + t]);
        float v4 = __ldg(&d_xw2[(size_t)s4 * H2 + t]);
        float v5 = __ldg(&d_xw2[(size_t)s5 * H2 + t]);
        float v6 = __ldg(&d_xw2[(size_t)s6 * H2 + t]);
        float v7 = __ldg(&d_xw2[(size_t)s7 * H2 + t]);
        float m0 = fmaxf(fmaxf(v0, v1), fmaxf(v2, v3));
        float m1 = fmaxf(fmaxf(v4, v5), fmaxf(v6, v7));
        m = fmaxf(m, fmaxf(m0, m1));
    }
    for (; e < e1; e++)
        m = fmaxf(m, __ldg(&d_xw2[(size_t)__ldg(&d_csr[e]) * H2 + t]));
    d_x2h[(size_t)hi * H2 + t] = fmaxf(d_dinv[node] * m + b2[t], 0.f);
}

// ---------------- self attention — r11 version (unchanged) -----------------
template <int F, int H>
__global__ void k_attn(const float* __restrict__ v, const int* __restrict__ hidx,
                       const float* __restrict__ aW, const float* __restrict__ ab,
                       const float* __restrict__ fW, const float* __restrict__ fb,
                       const float* __restrict__ gW, const float* __restrict__ gb) {
    int b = blockIdx.x;
    int t = threadIdx.x;           // 256
    int lane = t & 31, w = t >> 5; // 8 warps

    __shared__ float vsT[F][14];
    __shared__ float ls[NHOST * H];
    __shared__ float fs[NHOST * H];
    __shared__ float mx[NHOST], rinv[NHOST];
    __shared__ float outs[H];
    __shared__ float gs[H1];

    for (int i = t; i < NHOST * F; i += 256) {
        int h = i / F, f = i % F;
        int row = hidx ? hidx[b * NHOST + h] : (b * NHOST + h);
        vsT[f][h] = v[(size_t)row * F + f];
    }
    for (int f = t; f < F; f += 256) vsT[f][13] = 0.f;
    gs[t] = d_g[(size_t)b * H1 + t];
    __syncthreads();

    // Phase A: aL/fV for 13 hosts, 7 f32x2 pairs; f unrolled ×4
    if (t < H) {
        u64 aLp[7], fVp[7];
#pragma unroll
        for (int p = 0; p < 7; p++) { aLp[p] = 0ull; fVp[p] = 0ull; }
        for (int f = 0; f < F; f += 4) {
            float wa[4], wf[4];
#pragma unroll
            for (int j = 0; j < 4; j++) {
                wa[j] = __ldg(&aW[(f + j) * H + t]);
                wf[j] = __ldg(&fW[(f + j) * H + t]);
            }
#pragma unroll
            for (int j = 0; j < 4; j++) {
                u64 wa2, wf2;
                asm("mov.b64 %0, {%1, %1};" : "=l"(wa2) : "f"(wa[j]));
                asm("mov.b64 %0, {%1, %1};" : "=l"(wf2) : "f"(wf[j]));
#pragma unroll
                for (int p = 0; p < 7; p++) {
                    u64 xv = *reinterpret_cast<const u64*>(&vsT[f + j][2 * p]);
                    asm("fma.rn.f32x2 %0, %1, %2, %0;" : "+l"(aLp[p]) : "l"(xv), "l"(wa2));
                    asm("fma.rn.f32x2 %0, %1, %2, %0;" : "+l"(fVp[p]) : "l"(xv), "l"(wf2));
                }
            }
        }
        float abv = __ldg(&ab[t]), fbv = __ldg(&fb[t]);
#pragma unroll
        for (int p = 0; p < 7; p++) {
            float alo, ahi, flo, fhi;
            asm("mov.b64 {%0, %1}, %2;" : "=f"(alo), "=f"(ahi) : "l"(aLp[p]));
            asm("mov.b64 {%0, %1}, %2;" : "=f"(flo), "=f"(fhi) : "l"(fVp[p]));
            ls[(2 * p) * H + t] = alo + abv;
            fs[(2 * p) * H + t] = flo + fbv;
            if (2 * p + 1 < NHOST) {
                ls[(2 * p + 1) * H + t] = ahi + abv;
                fs[(2 * p + 1) * H + t] = fhi + fbv;
            }
        }
    }
    __syncthreads();

    // Phase B1: per-host max via warp reductions
    for (int h = w; h < NHOST; h += 8) {
        float m = -1e30f;
        for (int j = lane; j < H; j += 32) m = fmaxf(m, ls[h * H + j]);
#pragma unroll
        for (int d = 16; d > 0; d >>= 1) m = fmaxf(m, __shfl_xor_sync(0xffffffffu, m, d));
        if (lane == 0) mx[h] = m;
    }
    __syncthreads();
    // Phase B2: exp
    for (int i = t; i < NHOST * H; i += 256) ls[i] = expf(ls[i] - mx[i / H]);
    __syncthreads();
    // Phase B3: per-host sum via warp reductions
    for (int h = w; h < NHOST; h += 8) {
        float s = 0.f;
        for (int j = lane; j < H; j += 32) s += ls[h * H + j];
#pragma unroll
        for (int d = 16; d > 0; d >>= 1) s += __shfl_xor_sync(0xffffffffu, s, d);
        if (lane == 0) rinv[h] = 1.0f / s;
    }
    __syncthreads();

    // Phase C: weighted sum over hosts
    if (t < H) {
        float o = 0.f;
#pragma unroll
        for (int h = 0; h < NHOST; h++)
            o += ls[h * H + t] * rinv[h] * fs[h * H + t];
        outs[t] = o;
    }
    __syncthreads();

    // Phase D: g_new = concat(out,g) @ gW + gb ; g += g_new  (4 indep accs)
    float a0 = __ldg(&gb[t]), a1 = 0.f, a2 = 0.f, a3 = 0.f;
    for (int k = 0; k < H; k += 4) {
        a0 += outs[k]     * __ldg(&gW[(k)     * H1 + t]);
        a1 += outs[k + 1] * __ldg(&gW[(k + 1) * H1 + t]);
        a2 += outs[k + 2] * __ldg(&gW[(k + 2) * H1 + t]);
        a3 += outs[k + 3] * __ldg(&gW[(k + 3) * H1 + t]);
    }
    for (int k = 0; k < H1; k += 4) {
        a0 += gs[k]     * __ldg(&gW[(H + k)     * H1 + t]);
        a1 += gs[k + 1] * __ldg(&gW[(H + k + 1) * H1 + t]);
        a2 += gs[k + 2] * __ldg(&gW[(H + k + 2) * H1 + t]);
        a3 += gs[k + 3] * __ldg(&gW[(H + k + 3) * H1 + t]);
    }
    d_g[(size_t)b * H1 + t] = gs[t] + (a0 + a1) + (a2 + a3);
}

// ---------------- final head: relu(g@o1W+o1b)@o2W + o2b -------------------
__global__ void k_head(const float* __restrict__ o1W, const float* __restrict__ o1b,
                       const float* __restrict__ o2W, const float* __restrict__ o2b,
                       float* __restrict__ out) {
    int b = blockIdx.x;
    int t = threadIdx.x; // 64
    __shared__ float gs[H1];
    for (int i = t; i < H1; i += 64) gs[i] = d_g[(size_t)b * H1 + i];
    __syncthreads();
    float a0 = o1b[t], a1 = 0.f, a2 = 0.f, a3 = 0.f;
    for (int k = 0; k < H1; k += 4) {
        a0 += gs[k]     * __ldg(&o1W[(k)     * H2 + t]);
        a1 += gs[k + 1] * __ldg(&o1W[(k + 1) * H2 + t]);
        a2 += gs[k + 2] * __ldg(&o1W[(k + 2) * H2 + t]);
        a3 += gs[k + 3] * __ldg(&o1W[(k + 3) * H2 + t]);
    }
    float acc = (a0 + a1) + (a2 + a3);
    float v = fmaxf(acc, 0.f) * __ldg(&o2W[t]);
    __shared__ float rs[64];
    rs[t] = v;
    __syncthreads();
    if (t < 32) {
        float s = rs[t] + rs[t + 32];
#pragma unroll
        for (int d = 16; d > 0; d >>= 1) s += __shfl_down_sync(0xffffffffu, s, d);
        if (t == 0) out[b] = s + o2b[0];
    }
}

// ---------------- launch ---------------------------------------------------
extern "C" void kernel_launch(void* const* d_in, const int* in_sizes, int n_in,
                              void* d_out, int out_size) {
    const float* x       = (const float*)d_in[0];
    const int*   ei      = (const int*)d_in[1];
    const int*   hostidx = (const int*)d_in[2];
    const float* W1 = (const float*)d_in[3];
    const float* b1 = (const float*)d_in[4];
    const float* W2 = (const float*)d_in[5];
    const float* b2 = (const float*)d_in[6];
    const float* a0W = (const float*)d_in[7];  const float* a0b = (const float*)d_in[8];
    const float* f0W = (const float*)d_in[9];  const float* f0b = (const float*)d_in[10];
    const float* g0W = (const float*)d_in[11]; const float* g0b = (const float*)d_in[12];
    const float* a1W = (const float*)d_in[13]; const float* a1b = (const float*)d_in[14];
    const float* f1W = (const float*)d_in[15]; const float* f1b = (const float*)d_in[16];
    const float* g1W = (const float*)d_in[17]; const float* g1b = (const float*)d_in[18];
    const float* a2W = (const float*)d_in[19]; const float* a2b = (const float*)d_in[20];
    const float* f2W = (const float*)d_in[21]; const float* f2b = (const float*)d_in[22];
    const float* g2W = (const float*)d_in[23]; const float* g2b = (const float*)d_in[24];
    const float* o1W = (const float*)d_in[25]; const float* o1b = (const float*)d_in[26];
    const float* o2W = (const float*)d_in[27]; const float* o2b = (const float*)d_in[28];
    float* out = (float*)d_out;

    const int* src = ei;
    const int* dst = ei + EE;

    float* x1_ptr;  cudaGetSymbolAddress((void**)&x1_ptr,  d_x1);
    float* x2h_ptr; cudaGetSymbolAddress((void**)&x2h_ptr, d_x2h);

    k_zero<<<ZN / 256, 256>>>();                               // 1
    k_count_mh<<<(EE + 255) / 256, 256>>>(dst, hostidx);       // 2
    k_scan1<<<NB, 256>>>();                                    // 3
    // stage-0 attention — slot 4 → profiled (regression sentinel)
    k_attn<IN_F, H1><<<BB, 256>>>(x, hostidx, a0W, a0b, f0W, f0b, g0W, g0b);    // 4
    k_scan2<<<1, 256>>>();                                     // 5
    k_scan3<<<NB, 256>>>();                                    // 6
    k_gemm1<<<NN / G1R, 256>>>(x, W1);                         // 7
    k_fill_me<<<(EE + 255) / 256, 256>>>(src, dst);            // 8
    k_mklist<<<NN / 256, 256>>>();                             // 9

    // layer 1
    k_agg1<<<NN, 256>>>(b1);                                   // 10
    k_attn<H1, H1><<<BB, 256>>>(x1_ptr, hostidx, a1W, a1b, f1W, f1b, g1W, g1b); // 11

    // layer 2
    k_gemm2<<<(NN + G2R - 1) / G2R, 256>>>(W2);                // 12
    k_agg2<<<BB * NHOST, 64>>>(hostidx, b2);                   // 13
    k_attn<H2, H2><<<BB, 256>>>(x2h_ptr, (const int*)nullptr, a2W, a2b, f2W, f2b, g2W, g2b); // 14

    // head
    k_head<<<BB, 64>>>(o1W, o1b, o2W, o2b, out);               // 15
}